// round 1
// baseline (speedup 1.0000x reference)
#include <cuda_runtime.h>
#include <math.h>
#include <stdint.h>

// Problem dims (fixed by the reference):
//   B=16, T=1024, D=512, C=4096, DC=512, A=512, P=512
//   M_Q = B*T = 16384
//
// Pipeline:
//   q = ME @ Wq + bq           [16384,512]
//   k = CE @ Wk + bk           [4096,512]
//   v = CE @ Wv + bv           [4096,512]
//   s = (q @ k^T) * 1/sqrt(A)  [16384,4096]
//   s = softmax_rows(s)
//   x = s @ v                  [16384,512]
//   out = x @ Wo + bo          [16384,512]

// ---------------------------------------------------------------------------
// Scratch (device globals: allocation-free, reserved at module load)
// ---------------------------------------------------------------------------
__device__ float g_q[16384 * 512];
__device__ float g_k[4096 * 512];
__device__ float g_v[4096 * 512];
__device__ float g_s[(size_t)16384 * 4096];
__device__ float g_x[16384 * 512];

// ---------------------------------------------------------------------------
// SGEMM: C[M,N] = alpha * (A @ B) + bias,  A row-major [M,K].
// TRANS_B=false: B row-major [K,N].  TRANS_B=true: B row-major [N,K] (B^T).
// BM=BN=128, BK=8, 256 threads, 8x8 per-thread micro-tile.
// All of M,N,K are multiples of 128 here -> no bounds checks.
// ---------------------------------------------------------------------------
template <bool TRANS_B, bool HAS_BIAS>
__global__ __launch_bounds__(256, 2) void sgemm_kernel(
    const float* __restrict__ A, const float* __restrict__ Bm,
    const float* __restrict__ bias, float* __restrict__ C,
    int M, int N, int K, float alpha)
{
    constexpr int BM = 128, BN = 128, BK = 8, TM = 8, TN = 8;
    __shared__ float As[BK][BM];
    __shared__ float Bs[BK][BN];

    const int t = threadIdx.x;
    const int tx = t & 15;   // 0..15  (N direction)
    const int ty = t >> 4;   // 0..15  (M direction)
    const int rowBase = blockIdx.y * BM;
    const int colBase = blockIdx.x * BN;

    // A tile load mapping: 128 rows x 8 k, one float4 per thread.
    const int aRow = t >> 1;         // 0..127
    const int aK4  = (t & 1) * 4;    // 0 or 4

    float acc[TM][TN];
#pragma unroll
    for (int i = 0; i < TM; i++)
#pragma unroll
        for (int j = 0; j < TN; j++) acc[i][j] = 0.f;

    for (int k0 = 0; k0 < K; k0 += BK) {
        // --- load A tile (transposed into smem: As[k][row]) ---
        {
            float4 av = *reinterpret_cast<const float4*>(
                A + (size_t)(rowBase + aRow) * K + (k0 + aK4));
            As[aK4 + 0][aRow] = av.x;
            As[aK4 + 1][aRow] = av.y;
            As[aK4 + 2][aRow] = av.z;
            As[aK4 + 3][aRow] = av.w;
        }
        // --- load B tile into Bs[k][n] ---
        if (TRANS_B) {
            const int n  = t >> 1;        // 0..127
            const int k4 = (t & 1) * 4;   // 0 or 4
            float4 bv = *reinterpret_cast<const float4*>(
                Bm + (size_t)(colBase + n) * K + (k0 + k4));
            Bs[k4 + 0][n] = bv.x;
            Bs[k4 + 1][n] = bv.y;
            Bs[k4 + 2][n] = bv.z;
            Bs[k4 + 3][n] = bv.w;
        } else {
            const int kr = t >> 5;           // 0..7
            const int c4 = (t & 31) * 4;     // 0..124
            *reinterpret_cast<float4*>(&Bs[kr][c4]) =
                *reinterpret_cast<const float4*>(
                    Bm + (size_t)(k0 + kr) * N + (colBase + c4));
        }
        __syncthreads();

#pragma unroll
        for (int kk = 0; kk < BK; kk++) {
            float a_frag[TM], b_frag[TN];
            *reinterpret_cast<float4*>(&a_frag[0]) =
                *reinterpret_cast<float4*>(&As[kk][ty * TM + 0]);
            *reinterpret_cast<float4*>(&a_frag[4]) =
                *reinterpret_cast<float4*>(&As[kk][ty * TM + 4]);
            *reinterpret_cast<float4*>(&b_frag[0]) =
                *reinterpret_cast<float4*>(&Bs[kk][tx * TN + 0]);
            *reinterpret_cast<float4*>(&b_frag[4]) =
                *reinterpret_cast<float4*>(&Bs[kk][tx * TN + 4]);
#pragma unroll
            for (int i = 0; i < TM; i++)
#pragma unroll
                for (int j = 0; j < TN; j++)
                    acc[i][j] = fmaf(a_frag[i], b_frag[j], acc[i][j]);
        }
        __syncthreads();
    }

    // --- epilogue: scale + bias, vectorized stores ---
    float bfrag[TN];
#pragma unroll
    for (int j = 0; j < TN; j++)
        bfrag[j] = HAS_BIAS ? bias[colBase + tx * TN + j] : 0.f;

#pragma unroll
    for (int i = 0; i < TM; i++) {
        float* crow = C + (size_t)(rowBase + ty * TM + i) * N + colBase + tx * TN;
#pragma unroll
        for (int j4 = 0; j4 < TN; j4 += 4) {
            float4 r;
            r.x = acc[i][j4 + 0] * alpha + bfrag[j4 + 0];
            r.y = acc[i][j4 + 1] * alpha + bfrag[j4 + 1];
            r.z = acc[i][j4 + 2] * alpha + bfrag[j4 + 2];
            r.w = acc[i][j4 + 3] * alpha + bfrag[j4 + 3];
            *reinterpret_cast<float4*>(crow + j4) = r;
        }
    }
}

// ---------------------------------------------------------------------------
// Row softmax over 4096 columns, one block (256 threads) per row.
// Each thread handles 16 elements held in registers (4x float4) -> single
// global read + single global write per element.
// ---------------------------------------------------------------------------
__global__ __launch_bounds__(256) void softmax4096_kernel(float* __restrict__ S)
{
    float4* row = reinterpret_cast<float4*>(S + (size_t)blockIdx.x * 4096);
    const int tid = threadIdx.x;
    __shared__ float red[8];

    float4 v[4];
    float m = -INFINITY;
#pragma unroll
    for (int s = 0; s < 4; s++) {
        v[s] = row[tid + s * 256];
        m = fmaxf(m, fmaxf(fmaxf(v[s].x, v[s].y), fmaxf(v[s].z, v[s].w)));
    }
#pragma unroll
    for (int o = 16; o; o >>= 1) m = fmaxf(m, __shfl_xor_sync(0xffffffffu, m, o));
    if ((tid & 31) == 0) red[tid >> 5] = m;
    __syncthreads();
    float mAll = red[0];
#pragma unroll
    for (int w = 1; w < 8; w++) mAll = fmaxf(mAll, red[w]);
    __syncthreads();

    float sum = 0.f;
#pragma unroll
    for (int s = 0; s < 4; s++) {
        v[s].x = __expf(v[s].x - mAll);
        v[s].y = __expf(v[s].y - mAll);
        v[s].z = __expf(v[s].z - mAll);
        v[s].w = __expf(v[s].w - mAll);
        sum += (v[s].x + v[s].y) + (v[s].z + v[s].w);
    }
#pragma unroll
    for (int o = 16; o; o >>= 1) sum += __shfl_xor_sync(0xffffffffu, sum, o);
    if ((tid & 31) == 0) red[tid >> 5] = sum;
    __syncthreads();
    float sAll = 0.f;
#pragma unroll
    for (int w = 0; w < 8; w++) sAll += red[w];
    const float inv = 1.f / sAll;

#pragma unroll
    for (int s = 0; s < 4; s++) {
        float4 o4;
        o4.x = v[s].x * inv;
        o4.y = v[s].y * inv;
        o4.z = v[s].z * inv;
        o4.w = v[s].w * inv;
        row[tid + s * 256] = o4;
    }
}

// ---------------------------------------------------------------------------
// Launch
// ---------------------------------------------------------------------------
extern "C" void kernel_launch(void* const* d_in, const int* in_sizes, int n_in,
                              void* d_out, int out_size)
{
    const float* me = (const float*)d_in[0];  // [16,1024,512]
    const float* ce = (const float*)d_in[1];  // [4096,512]
    const float* Wq = (const float*)d_in[2];
    const float* bq = (const float*)d_in[3];
    const float* Wk = (const float*)d_in[4];
    const float* bk = (const float*)d_in[5];
    const float* Wv = (const float*)d_in[6];
    const float* bv = (const float*)d_in[7];
    const float* Wo = (const float*)d_in[8];
    const float* bo = (const float*)d_in[9];
    float* out = (float*)d_out;               // [16,1024,512] fp32

    float *q, *k, *v, *s, *x;
    cudaGetSymbolAddress((void**)&q, g_q);
    cudaGetSymbolAddress((void**)&k, g_k);
    cudaGetSymbolAddress((void**)&v, g_v);
    cudaGetSymbolAddress((void**)&s, g_s);
    cudaGetSymbolAddress((void**)&x, g_x);

    const int MQ = 16384, Cn = 4096, Ad = 512, Dd = 512, Pd = 512;
    const float scale = 0.044194173824159216f;  // 1/sqrt(512)
    dim3 blk(256);

    // q = ME @ Wq + bq : [16384,512] x [512,512]
    sgemm_kernel<false, true><<<dim3(Ad / 128, MQ / 128), blk>>>(
        me, Wq, bq, q, MQ, Ad, Dd, 1.f);
    // k = CE @ Wk + bk : [4096,512] x [512,512]
    sgemm_kernel<false, true><<<dim3(Ad / 128, Cn / 128), blk>>>(
        ce, Wk, bk, k, Cn, Ad, Dd, 1.f);
    // v = CE @ Wv + bv
    sgemm_kernel<false, true><<<dim3(Ad / 128, Cn / 128), blk>>>(
        ce, Wv, bv, v, Cn, Ad, Dd, 1.f);
    // s = scale * (q @ k^T) : [16384,512] x [4096,512]^T
    sgemm_kernel<true, false><<<dim3(Cn / 128, MQ / 128), blk>>>(
        q, k, nullptr, s, MQ, Cn, Ad, scale);
    // softmax over context dim
    softmax4096_kernel<<<MQ, 256>>>(s);
    // x = s @ v : [16384,4096] x [4096,512]
    sgemm_kernel<false, false><<<dim3(Ad / 128, MQ / 128), blk>>>(
        s, v, nullptr, x, MQ, Ad, Cn, 1.f);
    // out = x @ Wo + bo : [16384,512] x [512,512]
    sgemm_kernel<false, true><<<dim3(Pd / 128, MQ / 128), blk>>>(
        x, Wo, bo, out, MQ, Pd, Ad, 1.f);
}

// round 3
// speedup vs baseline: 2.0075x; 2.0075x over previous
#include <cuda_runtime.h>
#include <cuda_bf16.h>
#include <math.h>
#include <stdint.h>

// B=16, T=1024 (MQ=16384), D=512, C=4096, DC=512, A=512, P=512
//
// All GEMMs via warp-level mma.sync bf16 (HMMA) with hi/lo split:
//   C = Ah@Bh + Al@Bh + Ah@Bl   (fp32 accumulate)
// (tcgen05 is unavailable: harness PTX target is compute_103, not 103a.)

#define DINL __device__ __forceinline__

// ---------------------------------------------------------------------------
// Scratch
// ---------------------------------------------------------------------------
__device__ __align__(256) __nv_bfloat16 g_me_h[16384 * 512], g_me_l[16384 * 512];
__device__ __align__(256) __nv_bfloat16 g_ce_h[4096 * 512],  g_ce_l[4096 * 512];
__device__ __align__(256) __nv_bfloat16 g_wqt_h[512 * 512], g_wqt_l[512 * 512];
__device__ __align__(256) __nv_bfloat16 g_wkt_h[512 * 512], g_wkt_l[512 * 512];
__device__ __align__(256) __nv_bfloat16 g_wvt_h[512 * 512], g_wvt_l[512 * 512];
__device__ __align__(256) __nv_bfloat16 g_wot_h[512 * 512], g_wot_l[512 * 512];
__device__ __align__(256) __nv_bfloat16 g_q_h[16384 * 512], g_q_l[16384 * 512];
__device__ __align__(256) __nv_bfloat16 g_k_h[4096 * 512],  g_k_l[4096 * 512];
__device__ __align__(256) float         g_v[4096 * 512];
__device__ __align__(256) __nv_bfloat16 g_vt_h[512 * 4096], g_vt_l[512 * 4096];
__device__ __align__(256) float         g_s[(size_t)16384 * 4096];
__device__ __align__(256) __nv_bfloat16 g_p_h[(size_t)16384 * 4096];
__device__ __align__(256) __nv_bfloat16 g_p_l[(size_t)16384 * 4096];
__device__ __align__(256) __nv_bfloat16 g_x_h[16384 * 512], g_x_l[16384 * 512];

// ---------------------------------------------------------------------------
// Helpers
// ---------------------------------------------------------------------------
DINL uint32_t smem_u32(const void* p) {
    uint32_t a;
    asm("{ .reg .u64 t; cvta.to.shared.u64 t, %1; cvt.u32.u64 %0, t; }"
        : "=r"(a) : "l"(p));
    return a;
}
DINL void cp16(uint32_t dst, const void* src) {
    asm volatile("cp.async.cg.shared.global [%0], [%1], 16;"
                 :: "r"(dst), "l"(src) : "memory");
}
DINL void cp_commit() { asm volatile("cp.async.commit_group;" ::: "memory"); }
template <int N> DINL void cp_wait() {
    asm volatile("cp.async.wait_group %0;" :: "n"(N) : "memory");
}
DINL uint32_t lds32(uint32_t addr) {
    uint32_t v;
    asm volatile("ld.shared.b32 %0, [%1];" : "=r"(v) : "r"(addr));
    return v;
}
DINL void mma16816(float* c, const uint32_t* a, uint32_t b0, uint32_t b1) {
    asm volatile(
        "mma.sync.aligned.m16n8k16.row.col.f32.bf16.bf16.f32 "
        "{%0,%1,%2,%3}, {%4,%5,%6,%7}, {%8,%9}, {%0,%1,%2,%3};"
        : "+f"(c[0]), "+f"(c[1]), "+f"(c[2]), "+f"(c[3])
        : "r"(a[0]), "r"(a[1]), "r"(a[2]), "r"(a[3]), "r"(b0), "r"(b1));
}
DINL void split2(float y0, float y1, uint32_t& h2, uint32_t& l2) {
    __nv_bfloat162 h = __floats2bfloat162_rn(y0, y1);
    float r0 = y0 - __bfloat162float(__low2bfloat16(h));
    float r1 = y1 - __bfloat162float(__high2bfloat16(h));
    __nv_bfloat162 l = __floats2bfloat162_rn(r0, r1);
    h2 = *reinterpret_cast<uint32_t*>(&h);
    l2 = *reinterpret_cast<uint32_t*>(&l);
}

// ---------------------------------------------------------------------------
// Split-bf16 GEMM via mma.sync: C[M,N] = alpha*(A@B^T) (+bias)
//   A: [M,K] K-major bf16 hi/lo, B: [N,K] K-major bf16 hi/lo.
//   BM=BN=128, BK=32, 3-stage cp.async pipeline, 256 threads.
//   Warp grid 4(M) x 2(N); warp tile 32x64 = 2x8 mma tiles of m16n8k16.
//   Smem rows padded to 80B (20 banks) -> conflict-free 32-bit fragment loads.
// ---------------------------------------------------------------------------
constexpr int BM = 128, BN = 128, BK = 32, STAGES = 3;
constexpr int ROWB = 80;                    // bytes per smem row (32 bf16 + pad)
constexpr int STAGE_B = 128 * ROWB;         // 10240 B per operand stage
constexpr int SMEM_SZ = 2 * STAGES * STAGE_B;  // 61440 B

template <bool HAS_BIAS, bool OUT_SPLIT>
__global__ __launch_bounds__(256, 2) void mm_tc(
    const __nv_bfloat16* __restrict__ Ah, const __nv_bfloat16* __restrict__ Al,
    const __nv_bfloat16* __restrict__ Bh, const __nv_bfloat16* __restrict__ Bl,
    const float* __restrict__ bias, float alpha,
    float* __restrict__ outF, __nv_bfloat16* __restrict__ outH,
    __nv_bfloat16* __restrict__ outL, int M, int N, int K)
{
    extern __shared__ char smem[];
    const uint32_t sb = smem_u32(smem);
    const int t = threadIdx.x, wid = t >> 5, lane = t & 31;
    const int wm = wid & 3, wn = wid >> 2;      // warp coords: 4 x 2
    const int g = lane >> 2, tq = lane & 3;     // fragment coords
    const int rowBase = blockIdx.y * BM, colBase = blockIdx.x * BN;
    const int KC = K / BK, KT = 3 * KC;

    const __nv_bfloat16* aseg[3] = {Ah, Al, Ah};
    const __nv_bfloat16* bseg[3] = {Bh, Bh, Bl};

    float acc[2][8][4];
#pragma unroll
    for (int i = 0; i < 2; i++)
#pragma unroll
        for (int j = 0; j < 8; j++)
#pragma unroll
            for (int c = 0; c < 4; c++) acc[i][j][c] = 0.f;

    auto load_chunk = [&](int kt) {
        const int stage = kt % STAGES;
        const int seg = (kt >= 2 * KC) ? 2 : ((kt >= KC) ? 1 : 0);
        const size_t kOff = (size_t)(kt - seg * KC) * BK;
        const __nv_bfloat16* As = aseg[seg];
        const __nv_bfloat16* Bs = bseg[seg];
        const uint32_t aBase = sb + stage * STAGE_B;
        const uint32_t bBase = sb + (STAGES + stage) * STAGE_B;
#pragma unroll
        for (int i = 0; i < 2; i++) {
            const int chunk = t + i * 256;     // 0..511
            const int row = chunk >> 2;        // 0..127
            const int c16 = chunk & 3;         // 16B columns
            const uint32_t soff = row * ROWB + c16 * 16;
            cp16(aBase + soff, As + (size_t)(rowBase + row) * K + kOff + c16 * 8);
            cp16(bBase + soff, Bs + (size_t)(colBase + row) * K + kOff + c16 * 8);
        }
        cp_commit();
    };

    load_chunk(0);
    load_chunk(1);

    for (int kt = 0; kt < KT; kt++) {
        cp_wait<STAGES - 2>();
        __syncthreads();
        if (kt + STAGES - 1 < KT) load_chunk(kt + STAGES - 1);
        else cp_commit();  // keep group accounting uniform

        const int stage = kt % STAGES;
        const uint32_t aS = sb + stage * STAGE_B;
        const uint32_t bS = sb + (STAGES + stage) * STAGE_B;

#pragma unroll
        for (int kk = 0; kk < BK; kk += 16) {
            uint32_t a[2][4];
#pragma unroll
            for (int i = 0; i < 2; i++) {
                const uint32_t r0 = aS + (wm * 32 + i * 16 + g) * ROWB + (kk + 2 * tq) * 2;
                a[i][0] = lds32(r0);
                a[i][1] = lds32(r0 + 8 * ROWB);
                a[i][2] = lds32(r0 + 16);
                a[i][3] = lds32(r0 + 8 * ROWB + 16);
            }
#pragma unroll
            for (int j = 0; j < 8; j++) {
                const uint32_t br = bS + (wn * 64 + j * 8 + g) * ROWB + (kk + 2 * tq) * 2;
                const uint32_t b0 = lds32(br);
                const uint32_t b1 = lds32(br + 16);
                mma16816(acc[0][j], a[0], b0, b1);
                mma16816(acc[1][j], a[1], b0, b1);
            }
        }
        __syncthreads();
    }

    // --- epilogue ---
#pragma unroll
    for (int i = 0; i < 2; i++) {
        const int r0 = rowBase + wm * 32 + i * 16 + g;
#pragma unroll
        for (int j = 0; j < 8; j++) {
            const int col = colBase + wn * 64 + j * 8 + 2 * tq;
            float y0 = acc[i][j][0] * alpha, y1 = acc[i][j][1] * alpha;
            float y2 = acc[i][j][2] * alpha, y3 = acc[i][j][3] * alpha;
            if (HAS_BIAS) {
                const float b0 = __ldg(bias + col), b1 = __ldg(bias + col + 1);
                y0 += b0; y1 += b1; y2 += b0; y3 += b1;
            }
            if (OUT_SPLIT) {
                uint32_t h, l;
                split2(y0, y1, h, l);
                *reinterpret_cast<uint32_t*>(outH + (size_t)r0 * N + col) = h;
                *reinterpret_cast<uint32_t*>(outL + (size_t)r0 * N + col) = l;
                split2(y2, y3, h, l);
                *reinterpret_cast<uint32_t*>(outH + (size_t)(r0 + 8) * N + col) = h;
                *reinterpret_cast<uint32_t*>(outL + (size_t)(r0 + 8) * N + col) = l;
            } else {
                *reinterpret_cast<float2*>(outF + (size_t)r0 * N + col) =
                    make_float2(y0, y1);
                *reinterpret_cast<float2*>(outF + (size_t)(r0 + 8) * N + col) =
                    make_float2(y2, y3);
            }
        }
    }
}

// ---------------------------------------------------------------------------
// fp32 -> bf16 hi/lo elementwise
// ---------------------------------------------------------------------------
__global__ void convert_split_kernel(const float* __restrict__ in,
                                     __nv_bfloat16* __restrict__ oh,
                                     __nv_bfloat16* __restrict__ ol, int n4)
{
    int i = blockIdx.x * blockDim.x + threadIdx.x;
    if (i >= n4) return;
    float4 v = reinterpret_cast<const float4*>(in)[i];
    uint32_t h0, l0, h1, l1;
    split2(v.x, v.y, h0, l0);
    split2(v.z, v.w, h1, l1);
    reinterpret_cast<uint2*>(oh)[i] = make_uint2(h0, h1);
    reinterpret_cast<uint2*>(ol)[i] = make_uint2(l0, l1);
}

// ---------------------------------------------------------------------------
// fp32 [R,C] -> transposed bf16 hi/lo [C,R]
// ---------------------------------------------------------------------------
__global__ void transpose_split_kernel(const float* __restrict__ in,
                                       __nv_bfloat16* __restrict__ oh,
                                       __nv_bfloat16* __restrict__ ol,
                                       int R, int C)
{
    __shared__ float tile[32][33];
    const int cb = blockIdx.x * 32, r0 = blockIdx.y * 32;
    const int tx = threadIdx.x, ty = threadIdx.y;
#pragma unroll
    for (int i = ty; i < 32; i += 8)
        tile[i][tx] = in[(size_t)(r0 + i) * C + cb + tx];
    __syncthreads();
#pragma unroll
    for (int i = ty; i < 32; i += 8) {
        float v = tile[tx][i];
        __nv_bfloat16 h = __float2bfloat16(v);
        __nv_bfloat16 l = __float2bfloat16(v - __bfloat162float(h));
        oh[(size_t)(cb + i) * R + r0 + tx] = h;
        ol[(size_t)(cb + i) * R + r0 + tx] = l;
    }
}

// ---------------------------------------------------------------------------
// Row softmax over 4096 cols (fp32 in), bf16 hi/lo out
// ---------------------------------------------------------------------------
__global__ __launch_bounds__(256) void softmax4096_kernel(
    const float* __restrict__ S,
    __nv_bfloat16* __restrict__ Ph, __nv_bfloat16* __restrict__ Pl)
{
    const float4* row = reinterpret_cast<const float4*>(S + (size_t)blockIdx.x * 4096);
    const int tid = threadIdx.x;
    __shared__ float red[8];

    float4 v[4];
    float m = -INFINITY;
#pragma unroll
    for (int s = 0; s < 4; s++) {
        v[s] = row[tid + s * 256];
        m = fmaxf(m, fmaxf(fmaxf(v[s].x, v[s].y), fmaxf(v[s].z, v[s].w)));
    }
#pragma unroll
    for (int o = 16; o; o >>= 1) m = fmaxf(m, __shfl_xor_sync(0xffffffffu, m, o));
    if ((tid & 31) == 0) red[tid >> 5] = m;
    __syncthreads();
    float mAll = red[0];
#pragma unroll
    for (int w = 1; w < 8; w++) mAll = fmaxf(mAll, red[w]);
    __syncthreads();

    float sum = 0.f;
#pragma unroll
    for (int s = 0; s < 4; s++) {
        v[s].x = __expf(v[s].x - mAll);
        v[s].y = __expf(v[s].y - mAll);
        v[s].z = __expf(v[s].z - mAll);
        v[s].w = __expf(v[s].w - mAll);
        sum += (v[s].x + v[s].y) + (v[s].z + v[s].w);
    }
#pragma unroll
    for (int o = 16; o; o >>= 1) sum += __shfl_xor_sync(0xffffffffu, sum, o);
    if ((tid & 31) == 0) red[tid >> 5] = sum;
    __syncthreads();
    float sAll = 0.f;
#pragma unroll
    for (int w = 0; w < 8; w++) sAll += red[w];
    const float inv = 1.f / sAll;

    uint2* oh = reinterpret_cast<uint2*>(Ph + (size_t)blockIdx.x * 4096);
    uint2* ol = reinterpret_cast<uint2*>(Pl + (size_t)blockIdx.x * 4096);
#pragma unroll
    for (int s = 0; s < 4; s++) {
        uint32_t h0, l0, h1, l1;
        split2(v[s].x * inv, v[s].y * inv, h0, l0);
        split2(v[s].z * inv, v[s].w * inv, h1, l1);
        oh[tid + s * 256] = make_uint2(h0, h1);
        ol[tid + s * 256] = make_uint2(l0, l1);
    }
}

// ---------------------------------------------------------------------------
// Launch
// ---------------------------------------------------------------------------
extern "C" void kernel_launch(void* const* d_in, const int* in_sizes, int n_in,
                              void* d_out, int out_size)
{
    const float* me = (const float*)d_in[0];
    const float* ce = (const float*)d_in[1];
    const float* Wq = (const float*)d_in[2];
    const float* bq = (const float*)d_in[3];
    const float* Wk = (const float*)d_in[4];
    const float* bk = (const float*)d_in[5];
    const float* Wv = (const float*)d_in[6];
    const float* bv = (const float*)d_in[7];
    const float* Wo = (const float*)d_in[8];
    const float* bo = (const float*)d_in[9];
    float* out = (float*)d_out;

    cudaFuncSetAttribute(mm_tc<true, true>,   cudaFuncAttributeMaxDynamicSharedMemorySize, SMEM_SZ);
    cudaFuncSetAttribute(mm_tc<true, false>,  cudaFuncAttributeMaxDynamicSharedMemorySize, SMEM_SZ);
    cudaFuncSetAttribute(mm_tc<false, true>,  cudaFuncAttributeMaxDynamicSharedMemorySize, SMEM_SZ);
    cudaFuncSetAttribute(mm_tc<false, false>, cudaFuncAttributeMaxDynamicSharedMemorySize, SMEM_SZ);

    __nv_bfloat16 *me_h, *me_l, *ce_h, *ce_l, *wqt_h, *wqt_l, *wkt_h, *wkt_l;
    __nv_bfloat16 *wvt_h, *wvt_l, *wot_h, *wot_l, *q_h, *q_l, *k_h, *k_l;
    __nv_bfloat16 *vt_h, *vt_l, *p_h, *p_l, *x_h, *x_l;
    float *v, *s;
    cudaGetSymbolAddress((void**)&me_h, g_me_h);  cudaGetSymbolAddress((void**)&me_l, g_me_l);
    cudaGetSymbolAddress((void**)&ce_h, g_ce_h);  cudaGetSymbolAddress((void**)&ce_l, g_ce_l);
    cudaGetSymbolAddress((void**)&wqt_h, g_wqt_h); cudaGetSymbolAddress((void**)&wqt_l, g_wqt_l);
    cudaGetSymbolAddress((void**)&wkt_h, g_wkt_h); cudaGetSymbolAddress((void**)&wkt_l, g_wkt_l);
    cudaGetSymbolAddress((void**)&wvt_h, g_wvt_h); cudaGetSymbolAddress((void**)&wvt_l, g_wvt_l);
    cudaGetSymbolAddress((void**)&wot_h, g_wot_h); cudaGetSymbolAddress((void**)&wot_l, g_wot_l);
    cudaGetSymbolAddress((void**)&q_h, g_q_h);    cudaGetSymbolAddress((void**)&q_l, g_q_l);
    cudaGetSymbolAddress((void**)&k_h, g_k_h);    cudaGetSymbolAddress((void**)&k_l, g_k_l);
    cudaGetSymbolAddress((void**)&v, g_v);
    cudaGetSymbolAddress((void**)&vt_h, g_vt_h);  cudaGetSymbolAddress((void**)&vt_l, g_vt_l);
    cudaGetSymbolAddress((void**)&s, g_s);
    cudaGetSymbolAddress((void**)&p_h, g_p_h);    cudaGetSymbolAddress((void**)&p_l, g_p_l);
    cudaGetSymbolAddress((void**)&x_h, g_x_h);    cudaGetSymbolAddress((void**)&x_l, g_x_l);

    const int MQ = 16384, Cn = 4096, Ad = 512, Dd = 512, Pd = 512;
    const float scale = 0.044194173824159216f;  // 1/sqrt(512)

    convert_split_kernel<<<(MQ * Dd / 4 + 255) / 256, 256>>>(me, me_h, me_l, MQ * Dd / 4);
    convert_split_kernel<<<(Cn * Dd / 4 + 255) / 256, 256>>>(ce, ce_h, ce_l, Cn * Dd / 4);
    dim3 tb(32, 8);
    transpose_split_kernel<<<dim3(16, 16), tb>>>(Wq, wqt_h, wqt_l, Dd, Ad);
    transpose_split_kernel<<<dim3(16, 16), tb>>>(Wk, wkt_h, wkt_l, Dd, Ad);
    transpose_split_kernel<<<dim3(16, 16), tb>>>(Wv, wvt_h, wvt_l, Dd, Ad);
    transpose_split_kernel<<<dim3(16, 16), tb>>>(Wo, wot_h, wot_l, Ad, Pd);

    // q = ME @ Wq + bq  -> split
    mm_tc<true, true><<<dim3(Ad / BN, MQ / BM), 256, SMEM_SZ>>>(
        me_h, me_l, wqt_h, wqt_l, bq, 1.f, nullptr, q_h, q_l, MQ, Ad, Dd);
    // k = CE @ Wk + bk  -> split
    mm_tc<true, true><<<dim3(Ad / BN, Cn / BM), 256, SMEM_SZ>>>(
        ce_h, ce_l, wkt_h, wkt_l, bk, 1.f, nullptr, k_h, k_l, Cn, Ad, Dd);
    // v = CE @ Wv + bv  -> fp32
    mm_tc<true, false><<<dim3(Ad / BN, Cn / BM), 256, SMEM_SZ>>>(
        ce_h, ce_l, wvt_h, wvt_l, bv, 1.f, v, nullptr, nullptr, Cn, Ad, Dd);
    // vt = v^T -> split
    transpose_split_kernel<<<dim3(Ad / 32, Cn / 32), tb>>>(v, vt_h, vt_l, Cn, Ad);
    // s = scale * q @ k^T -> fp32
    mm_tc<false, false><<<dim3(Cn / BN, MQ / BM), 256, SMEM_SZ>>>(
        q_h, q_l, k_h, k_l, nullptr, scale, s, nullptr, nullptr, MQ, Cn, Ad);
    // p = softmax(s) -> split
    softmax4096_kernel<<<MQ, 256>>>(s, p_h, p_l);
    // x = p @ vt^T -> split
    mm_tc<false, true><<<dim3(Ad / BN, MQ / BM), 256, SMEM_SZ>>>(
        p_h, p_l, vt_h, vt_l, nullptr, 1.f, nullptr, x_h, x_l, MQ, Ad, Cn);
    // out = x @ Wo + bo -> fp32
    mm_tc<true, false><<<dim3(Pd / BN, MQ / BM), 256, SMEM_SZ>>>(
        x_h, x_l, wot_h, wot_l, bo, 1.f, out, nullptr, nullptr, MQ, Pd, Ad);
}

// round 4
// speedup vs baseline: 2.0631x; 1.0277x over previous
#include <cuda_runtime.h>
#include <cuda_bf16.h>
#include <math.h>
#include <stdint.h>

// B=16, T=1024 (MQ=16384), D=512, C=4096, DC=512, A=512, P=512
//
// All GEMMs via warp-level mma.sync bf16 (HMMA) with hi/lo split:
//   C = Ah@Bh + Al@Bh + Ah@Bl   (fp32 accumulate)
// Fragment loads via ldmatrix.x4 (6 LDSM + 16 HMMA per k16 per warp).

#define DINL __device__ __forceinline__

// ---------------------------------------------------------------------------
// Scratch
// ---------------------------------------------------------------------------
__device__ __align__(256) __nv_bfloat16 g_me_h[16384 * 512], g_me_l[16384 * 512];
__device__ __align__(256) __nv_bfloat16 g_ce_h[4096 * 512],  g_ce_l[4096 * 512];
__device__ __align__(256) __nv_bfloat16 g_wqt_h[512 * 512], g_wqt_l[512 * 512];
__device__ __align__(256) __nv_bfloat16 g_wkt_h[512 * 512], g_wkt_l[512 * 512];
__device__ __align__(256) __nv_bfloat16 g_wvt_h[512 * 512], g_wvt_l[512 * 512];
__device__ __align__(256) __nv_bfloat16 g_wot_h[512 * 512], g_wot_l[512 * 512];
__device__ __align__(256) __nv_bfloat16 g_q_h[16384 * 512], g_q_l[16384 * 512];
__device__ __align__(256) __nv_bfloat16 g_k_h[4096 * 512],  g_k_l[4096 * 512];
__device__ __align__(256) float         g_v[4096 * 512];
__device__ __align__(256) __nv_bfloat16 g_vt_h[512 * 4096], g_vt_l[512 * 4096];
__device__ __align__(256) float         g_s[(size_t)16384 * 4096];
__device__ __align__(256) __nv_bfloat16 g_p_h[(size_t)16384 * 4096];
__device__ __align__(256) __nv_bfloat16 g_p_l[(size_t)16384 * 4096];
__device__ __align__(256) __nv_bfloat16 g_x_h[16384 * 512], g_x_l[16384 * 512];

// ---------------------------------------------------------------------------
// Helpers
// ---------------------------------------------------------------------------
DINL uint32_t smem_u32(const void* p) {
    uint32_t a;
    asm("{ .reg .u64 t; cvta.to.shared.u64 t, %1; cvt.u32.u64 %0, t; }"
        : "=r"(a) : "l"(p));
    return a;
}
DINL void cp16(uint32_t dst, const void* src) {
    asm volatile("cp.async.cg.shared.global [%0], [%1], 16;"
                 :: "r"(dst), "l"(src) : "memory");
}
DINL void cp_commit() { asm volatile("cp.async.commit_group;" ::: "memory"); }
template <int N> DINL void cp_wait() {
    asm volatile("cp.async.wait_group %0;" :: "n"(N) : "memory");
}
DINL void ldsm4(uint32_t* r, uint32_t addr) {
    asm volatile("ldmatrix.sync.aligned.m8n8.x4.shared.b16 {%0,%1,%2,%3}, [%4];"
                 : "=r"(r[0]), "=r"(r[1]), "=r"(r[2]), "=r"(r[3]) : "r"(addr));
}
DINL void mma16816(float* c, const uint32_t* a, uint32_t b0, uint32_t b1) {
    asm volatile(
        "mma.sync.aligned.m16n8k16.row.col.f32.bf16.bf16.f32 "
        "{%0,%1,%2,%3}, {%4,%5,%6,%7}, {%8,%9}, {%0,%1,%2,%3};"
        : "+f"(c[0]), "+f"(c[1]), "+f"(c[2]), "+f"(c[3])
        : "r"(a[0]), "r"(a[1]), "r"(a[2]), "r"(a[3]), "r"(b0), "r"(b1));
}
DINL void split2(float y0, float y1, uint32_t& h2, uint32_t& l2) {
    __nv_bfloat162 h = __floats2bfloat162_rn(y0, y1);
    float r0 = y0 - __bfloat162float(__low2bfloat16(h));
    float r1 = y1 - __bfloat162float(__high2bfloat16(h));
    __nv_bfloat162 l = __floats2bfloat162_rn(r0, r1);
    h2 = *reinterpret_cast<uint32_t*>(&h);
    l2 = *reinterpret_cast<uint32_t*>(&l);
}

// ---------------------------------------------------------------------------
// Split-bf16 GEMM via mma.sync + ldmatrix: C[M,N] = alpha*(A@B^T) (+bias)
//   A: [M,K] K-major bf16 hi/lo, B: [N,K] K-major bf16 hi/lo.
//   BM=BN=128, BK=32, 4-stage cp.async pipeline, 256 threads.
//   Warp grid 4(M) x 2(N); warp tile 32x64 = 2x8 mma tiles of m16n8k16.
//   Smem rows padded to 80B (20 banks): ldmatrix row stride = 20 banks ->
//   8 rows cover all 32 banks exactly once per phase (conflict-free).
// ---------------------------------------------------------------------------
constexpr int BM = 128, BN = 128, BK = 32, STAGES = 4;
constexpr int ROWB = 80;                    // bytes per smem row (32 bf16 + pad)
constexpr int STAGE_B = 128 * ROWB;         // 10240 B per operand stage
constexpr int SMEM_SZ = 2 * STAGES * STAGE_B;  // 81920 B

template <bool HAS_BIAS, bool OUT_SPLIT>
__global__ __launch_bounds__(256, 2) void mm_tc(
    const __nv_bfloat16* __restrict__ Ah, const __nv_bfloat16* __restrict__ Al,
    const __nv_bfloat16* __restrict__ Bh, const __nv_bfloat16* __restrict__ Bl,
    const float* __restrict__ bias, float alpha,
    float* __restrict__ outF, __nv_bfloat16* __restrict__ outH,
    __nv_bfloat16* __restrict__ outL, int M, int N, int K)
{
    extern __shared__ char smem[];
    const uint32_t sb = smem_u32(smem);
    const int t = threadIdx.x, wid = t >> 5, lane = t & 31;
    const int wm = wid & 3, wn = wid >> 2;      // warp coords: 4 x 2
    const int g = lane >> 2, tq = lane & 3;     // fragment coords
    const uint32_t lrow = lane & 15;            // ldmatrix row within 16
    const uint32_t lcol = (lane >> 4) * 16;     // ldmatrix 16B column select
    const int rowBase = blockIdx.y * BM, colBase = blockIdx.x * BN;
    const int KC = K / BK, KT = 3 * KC;

    const __nv_bfloat16* aseg[3] = {Ah, Al, Ah};
    const __nv_bfloat16* bseg[3] = {Bh, Bh, Bl};

    float acc[2][8][4];
#pragma unroll
    for (int i = 0; i < 2; i++)
#pragma unroll
        for (int j = 0; j < 8; j++)
#pragma unroll
            for (int c = 0; c < 4; c++) acc[i][j][c] = 0.f;

    auto load_chunk = [&](int kt) {
        const int stage = kt % STAGES;
        const int seg = (kt >= 2 * KC) ? 2 : ((kt >= KC) ? 1 : 0);
        const size_t kOff = (size_t)(kt - seg * KC) * BK;
        const __nv_bfloat16* As = aseg[seg];
        const __nv_bfloat16* Bs = bseg[seg];
        const uint32_t aBase = sb + stage * STAGE_B;
        const uint32_t bBase = sb + (STAGES + stage) * STAGE_B;
#pragma unroll
        for (int i = 0; i < 2; i++) {
            const int chunk = t + i * 256;     // 0..511
            const int row = chunk >> 2;        // 0..127
            const int c16 = chunk & 3;         // 16B columns
            const uint32_t soff = row * ROWB + c16 * 16;
            cp16(aBase + soff, As + (size_t)(rowBase + row) * K + kOff + c16 * 8);
            cp16(bBase + soff, Bs + (size_t)(colBase + row) * K + kOff + c16 * 8);
        }
        cp_commit();
    };

    for (int i = 0; i < STAGES - 1; i++) load_chunk(i);

    for (int kt = 0; kt < KT; kt++) {
        cp_wait<STAGES - 2>();
        __syncthreads();
        if (kt + STAGES - 1 < KT) load_chunk(kt + STAGES - 1);
        else cp_commit();  // keep group accounting uniform

        const int stage = kt % STAGES;
        const uint32_t aS = sb + stage * STAGE_B;
        const uint32_t bS = sb + (STAGES + stage) * STAGE_B;

#pragma unroll
        for (int kk = 0; kk < BK; kk += 16) {
            uint32_t a[2][4];
            ldsm4(a[0], aS + (wm * 32 + 0  + lrow) * ROWB + kk * 2 + lcol);
            ldsm4(a[1], aS + (wm * 32 + 16 + lrow) * ROWB + kk * 2 + lcol);
#pragma unroll
            for (int j2 = 0; j2 < 4; j2++) {
                uint32_t b[4];
                ldsm4(b, bS + (wn * 64 + j2 * 16 + lrow) * ROWB + kk * 2 + lcol);
                // b[0],b[2] = (k0,k8) of n-tile 2*j2 ; b[1],b[3] = n-tile 2*j2+1
                mma16816(acc[0][2 * j2 + 0], a[0], b[0], b[2]);
                mma16816(acc[1][2 * j2 + 0], a[1], b[0], b[2]);
                mma16816(acc[0][2 * j2 + 1], a[0], b[1], b[3]);
                mma16816(acc[1][2 * j2 + 1], a[1], b[1], b[3]);
            }
        }
        __syncthreads();
    }

    // --- epilogue ---
#pragma unroll
    for (int i = 0; i < 2; i++) {
        const int r0 = rowBase + wm * 32 + i * 16 + g;
#pragma unroll
        for (int j = 0; j < 8; j++) {
            const int col = colBase + wn * 64 + j * 8 + 2 * tq;
            float y0 = acc[i][j][0] * alpha, y1 = acc[i][j][1] * alpha;
            float y2 = acc[i][j][2] * alpha, y3 = acc[i][j][3] * alpha;
            if (HAS_BIAS) {
                const float b0 = __ldg(bias + col), b1 = __ldg(bias + col + 1);
                y0 += b0; y1 += b1; y2 += b0; y3 += b1;
            }
            if (OUT_SPLIT) {
                uint32_t h, l;
                split2(y0, y1, h, l);
                *reinterpret_cast<uint32_t*>(outH + (size_t)r0 * N + col) = h;
                *reinterpret_cast<uint32_t*>(outL + (size_t)r0 * N + col) = l;
                split2(y2, y3, h, l);
                *reinterpret_cast<uint32_t*>(outH + (size_t)(r0 + 8) * N + col) = h;
                *reinterpret_cast<uint32_t*>(outL + (size_t)(r0 + 8) * N + col) = l;
            } else {
                *reinterpret_cast<float2*>(outF + (size_t)r0 * N + col) =
                    make_float2(y0, y1);
                *reinterpret_cast<float2*>(outF + (size_t)(r0 + 8) * N + col) =
                    make_float2(y2, y3);
            }
        }
    }
}

// ---------------------------------------------------------------------------
// fp32 -> bf16 hi/lo elementwise
// ---------------------------------------------------------------------------
__global__ void convert_split_kernel(const float* __restrict__ in,
                                     __nv_bfloat16* __restrict__ oh,
                                     __nv_bfloat16* __restrict__ ol, int n4)
{
    int i = blockIdx.x * blockDim.x + threadIdx.x;
    if (i >= n4) return;
    float4 v = reinterpret_cast<const float4*>(in)[i];
    uint32_t h0, l0, h1, l1;
    split2(v.x, v.y, h0, l0);
    split2(v.z, v.w, h1, l1);
    reinterpret_cast<uint2*>(oh)[i] = make_uint2(h0, h1);
    reinterpret_cast<uint2*>(ol)[i] = make_uint2(l0, l1);
}

// ---------------------------------------------------------------------------
// fp32 [R,C] -> transposed bf16 hi/lo [C,R]
// ---------------------------------------------------------------------------
__global__ void transpose_split_kernel(const float* __restrict__ in,
                                       __nv_bfloat16* __restrict__ oh,
                                       __nv_bfloat16* __restrict__ ol,
                                       int R, int C)
{
    __shared__ float tile[32][33];
    const int cb = blockIdx.x * 32, r0 = blockIdx.y * 32;
    const int tx = threadIdx.x, ty = threadIdx.y;
#pragma unroll
    for (int i = ty; i < 32; i += 8)
        tile[i][tx] = in[(size_t)(r0 + i) * C + cb + tx];
    __syncthreads();
#pragma unroll
    for (int i = ty; i < 32; i += 8) {
        float v = tile[tx][i];
        __nv_bfloat16 h = __float2bfloat16(v);
        __nv_bfloat16 l = __float2bfloat16(v - __bfloat162float(h));
        oh[(size_t)(cb + i) * R + r0 + tx] = h;
        ol[(size_t)(cb + i) * R + r0 + tx] = l;
    }
}

// ---------------------------------------------------------------------------
// Row softmax over 4096 cols (fp32 in), bf16 hi/lo out
// ---------------------------------------------------------------------------
__global__ __launch_bounds__(256) void softmax4096_kernel(
    const float* __restrict__ S,
    __nv_bfloat16* __restrict__ Ph, __nv_bfloat16* __restrict__ Pl)
{
    const float4* row = reinterpret_cast<const float4*>(S + (size_t)blockIdx.x * 4096);
    const int tid = threadIdx.x;
    __shared__ float red[8];

    float4 v[4];
    float m = -INFINITY;
#pragma unroll
    for (int s = 0; s < 4; s++) {
        v[s] = row[tid + s * 256];
        m = fmaxf(m, fmaxf(fmaxf(v[s].x, v[s].y), fmaxf(v[s].z, v[s].w)));
    }
#pragma unroll
    for (int o = 16; o; o >>= 1) m = fmaxf(m, __shfl_xor_sync(0xffffffffu, m, o));
    if ((tid & 31) == 0) red[tid >> 5] = m;
    __syncthreads();
    float mAll = red[0];
#pragma unroll
    for (int w = 1; w < 8; w++) mAll = fmaxf(mAll, red[w]);
    __syncthreads();

    float sum = 0.f;
#pragma unroll
    for (int s = 0; s < 4; s++) {
        v[s].x = __expf(v[s].x - mAll);
        v[s].y = __expf(v[s].y - mAll);
        v[s].z = __expf(v[s].z - mAll);
        v[s].w = __expf(v[s].w - mAll);
        sum += (v[s].x + v[s].y) + (v[s].z + v[s].w);
    }
#pragma unroll
    for (int o = 16; o; o >>= 1) sum += __shfl_xor_sync(0xffffffffu, sum, o);
    if ((tid & 31) == 0) red[tid >> 5] = sum;
    __syncthreads();
    float sAll = 0.f;
#pragma unroll
    for (int w = 0; w < 8; w++) sAll += red[w];
    const float inv = 1.f / sAll;

    uint2* oh = reinterpret_cast<uint2*>(Ph + (size_t)blockIdx.x * 4096);
    uint2* ol = reinterpret_cast<uint2*>(Pl + (size_t)blockIdx.x * 4096);
#pragma unroll
    for (int s = 0; s < 4; s++) {
        uint32_t h0, l0, h1, l1;
        split2(v[s].x * inv, v[s].y * inv, h0, l0);
        split2(v[s].z * inv, v[s].w * inv, h1, l1);
        oh[tid + s * 256] = make_uint2(h0, h1);
        ol[tid + s * 256] = make_uint2(l0, l1);
    }
}

// ---------------------------------------------------------------------------
// Launch
// ---------------------------------------------------------------------------
extern "C" void kernel_launch(void* const* d_in, const int* in_sizes, int n_in,
                              void* d_out, int out_size)
{
    const float* me = (const float*)d_in[0];
    const float* ce = (const float*)d_in[1];
    const float* Wq = (const float*)d_in[2];
    const float* bq = (const float*)d_in[3];
    const float* Wk = (const float*)d_in[4];
    const float* bk = (const float*)d_in[5];
    const float* Wv = (const float*)d_in[6];
    const float* bv = (const float*)d_in[7];
    const float* Wo = (const float*)d_in[8];
    const float* bo = (const float*)d_in[9];
    float* out = (float*)d_out;

    cudaFuncSetAttribute(mm_tc<true, true>,   cudaFuncAttributeMaxDynamicSharedMemorySize, SMEM_SZ);
    cudaFuncSetAttribute(mm_tc<true, false>,  cudaFuncAttributeMaxDynamicSharedMemorySize, SMEM_SZ);
    cudaFuncSetAttribute(mm_tc<false, true>,  cudaFuncAttributeMaxDynamicSharedMemorySize, SMEM_SZ);
    cudaFuncSetAttribute(mm_tc<false, false>, cudaFuncAttributeMaxDynamicSharedMemorySize, SMEM_SZ);

    __nv_bfloat16 *me_h, *me_l, *ce_h, *ce_l, *wqt_h, *wqt_l, *wkt_h, *wkt_l;
    __nv_bfloat16 *wvt_h, *wvt_l, *wot_h, *wot_l, *q_h, *q_l, *k_h, *k_l;
    __nv_bfloat16 *vt_h, *vt_l, *p_h, *p_l, *x_h, *x_l;
    float *v, *s;
    cudaGetSymbolAddress((void**)&me_h, g_me_h);  cudaGetSymbolAddress((void**)&me_l, g_me_l);
    cudaGetSymbolAddress((void**)&ce_h, g_ce_h);  cudaGetSymbolAddress((void**)&ce_l, g_ce_l);
    cudaGetSymbolAddress((void**)&wqt_h, g_wqt_h); cudaGetSymbolAddress((void**)&wqt_l, g_wqt_l);
    cudaGetSymbolAddress((void**)&wkt_h, g_wkt_h); cudaGetSymbolAddress((void**)&wkt_l, g_wkt_l);
    cudaGetSymbolAddress((void**)&wvt_h, g_wvt_h); cudaGetSymbolAddress((void**)&wvt_l, g_wvt_l);
    cudaGetSymbolAddress((void**)&wot_h, g_wot_h); cudaGetSymbolAddress((void**)&wot_l, g_wot_l);
    cudaGetSymbolAddress((void**)&q_h, g_q_h);    cudaGetSymbolAddress((void**)&q_l, g_q_l);
    cudaGetSymbolAddress((void**)&k_h, g_k_h);    cudaGetSymbolAddress((void**)&k_l, g_k_l);
    cudaGetSymbolAddress((void**)&v, g_v);
    cudaGetSymbolAddress((void**)&vt_h, g_vt_h);  cudaGetSymbolAddress((void**)&vt_l, g_vt_l);
    cudaGetSymbolAddress((void**)&s, g_s);
    cudaGetSymbolAddress((void**)&p_h, g_p_h);    cudaGetSymbolAddress((void**)&p_l, g_p_l);
    cudaGetSymbolAddress((void**)&x_h, g_x_h);    cudaGetSymbolAddress((void**)&x_l, g_x_l);

    const int MQ = 16384, Cn = 4096, Ad = 512, Dd = 512, Pd = 512;
    const float scale = 0.044194173824159216f;  // 1/sqrt(512)

    convert_split_kernel<<<(MQ * Dd / 4 + 255) / 256, 256>>>(me, me_h, me_l, MQ * Dd / 4);
    convert_split_kernel<<<(Cn * Dd / 4 + 255) / 256, 256>>>(ce, ce_h, ce_l, Cn * Dd / 4);
    dim3 tb(32, 8);
    transpose_split_kernel<<<dim3(16, 16), tb>>>(Wq, wqt_h, wqt_l, Dd, Ad);
    transpose_split_kernel<<<dim3(16, 16), tb>>>(Wk, wkt_h, wkt_l, Dd, Ad);
    transpose_split_kernel<<<dim3(16, 16), tb>>>(Wv, wvt_h, wvt_l, Dd, Ad);
    transpose_split_kernel<<<dim3(16, 16), tb>>>(Wo, wot_h, wot_l, Ad, Pd);

    // q = ME @ Wq + bq  -> split
    mm_tc<true, true><<<dim3(Ad / BN, MQ / BM), 256, SMEM_SZ>>>(
        me_h, me_l, wqt_h, wqt_l, bq, 1.f, nullptr, q_h, q_l, MQ, Ad, Dd);
    // k = CE @ Wk + bk  -> split
    mm_tc<true, true><<<dim3(Ad / BN, Cn / BM), 256, SMEM_SZ>>>(
        ce_h, ce_l, wkt_h, wkt_l, bk, 1.f, nullptr, k_h, k_l, Cn, Ad, Dd);
    // v = CE @ Wv + bv  -> fp32
    mm_tc<true, false><<<dim3(Ad / BN, Cn / BM), 256, SMEM_SZ>>>(
        ce_h, ce_l, wvt_h, wvt_l, bv, 1.f, v, nullptr, nullptr, Cn, Ad, Dd);
    // vt = v^T -> split
    transpose_split_kernel<<<dim3(Ad / 32, Cn / 32), tb>>>(v, vt_h, vt_l, Cn, Ad);
    // s = scale * q @ k^T -> fp32
    mm_tc<false, false><<<dim3(Cn / BN, MQ / BM), 256, SMEM_SZ>>>(
        q_h, q_l, k_h, k_l, nullptr, scale, s, nullptr, nullptr, MQ, Cn, Ad);
    // p = softmax(s) -> split
    softmax4096_kernel<<<MQ, 256>>>(s, p_h, p_l);
    // x = p @ vt^T -> split
    mm_tc<false, true><<<dim3(Ad / BN, MQ / BM), 256, SMEM_SZ>>>(
        p_h, p_l, vt_h, vt_l, nullptr, 1.f, nullptr, x_h, x_l, MQ, Ad, Cn);
    // out = x @ Wo + bo -> fp32
    mm_tc<true, false><<<dim3(Pd / BN, MQ / BM), 256, SMEM_SZ>>>(
        x_h, x_l, wot_h, wot_l, bo, 1.f, out, nullptr, nullptr, MQ, Pd, Ad);
}

// round 5
// speedup vs baseline: 4.3904x; 2.1281x over previous
#include <cuda_runtime.h>
#include <cuda_fp16.h>
#include <math.h>
#include <stdint.h>

// B=16, T=1024 (MQ=16384), D=512, C=4096, DC=512, A=512, P=512
//
// mma.sync fp16 (fp32 accum). Projections q/k/v/out use 3-term hi/lo split
// (error ~2^-22); the big scores/PV GEMMs run single-pass fp16 (~2.4e-4 rms).
// Softmax emits unnormalized exp in fp16 + inv_sum; PV epilogue normalizes.

#define DINL __device__ __forceinline__

// ---------------------------------------------------------------------------
// Scratch
// ---------------------------------------------------------------------------
__device__ __align__(256) __half g_me_h[16384 * 512], g_me_l[16384 * 512];
__device__ __align__(256) __half g_ce_h[4096 * 512],  g_ce_l[4096 * 512];
__device__ __align__(256) __half g_wqt_h[512 * 512], g_wqt_l[512 * 512];
__device__ __align__(256) __half g_wkt_h[512 * 512], g_wkt_l[512 * 512];
__device__ __align__(256) __half g_wvt_h[512 * 512], g_wvt_l[512 * 512];
__device__ __align__(256) __half g_wot_h[512 * 512], g_wot_l[512 * 512];
__device__ __align__(256) __half g_q[16384 * 512];
__device__ __align__(256) __half g_k[4096 * 512];
__device__ __align__(256) float  g_v[4096 * 512];
__device__ __align__(256) __half g_vt[512 * 4096];
__device__ __align__(256) float  g_s[(size_t)16384 * 4096];
__device__ __align__(256) __half g_e[(size_t)16384 * 4096];
__device__ __align__(256) float  g_invsum[16384];
__device__ __align__(256) __half g_x_h[16384 * 512], g_x_l[16384 * 512];

// ---------------------------------------------------------------------------
// Helpers
// ---------------------------------------------------------------------------
DINL uint32_t smem_u32(const void* p) {
    uint32_t a;
    asm("{ .reg .u64 t; cvta.to.shared.u64 t, %1; cvt.u32.u64 %0, t; }"
        : "=r"(a) : "l"(p));
    return a;
}
DINL void cp16(uint32_t dst, const void* src) {
    asm volatile("cp.async.cg.shared.global [%0], [%1], 16;"
                 :: "r"(dst), "l"(src) : "memory");
}
DINL void cp_commit() { asm volatile("cp.async.commit_group;" ::: "memory"); }
template <int N> DINL void cp_wait() {
    asm volatile("cp.async.wait_group %0;" :: "n"(N) : "memory");
}
DINL void ldsm4(uint32_t* r, uint32_t addr) {
    asm volatile("ldmatrix.sync.aligned.m8n8.x4.shared.b16 {%0,%1,%2,%3}, [%4];"
                 : "=r"(r[0]), "=r"(r[1]), "=r"(r[2]), "=r"(r[3]) : "r"(addr));
}
DINL void mma16816(float* c, const uint32_t* a, uint32_t b0, uint32_t b1) {
    asm volatile(
        "mma.sync.aligned.m16n8k16.row.col.f32.f16.f16.f32 "
        "{%0,%1,%2,%3}, {%4,%5,%6,%7}, {%8,%9}, {%0,%1,%2,%3};"
        : "+f"(c[0]), "+f"(c[1]), "+f"(c[2]), "+f"(c[3])
        : "r"(a[0]), "r"(a[1]), "r"(a[2]), "r"(a[3]), "r"(b0), "r"(b1));
}
DINL void split2h(float y0, float y1, uint32_t& h2, uint32_t& l2) {
    __half2 h = __floats2half2_rn(y0, y1);
    float r0 = y0 - __low2float(h);
    float r1 = y1 - __high2float(h);
    __half2 l = __floats2half2_rn(r0, r1);
    h2 = *reinterpret_cast<uint32_t*>(&h);
    l2 = *reinterpret_cast<uint32_t*>(&l);
}
DINL uint32_t pack2h(float y0, float y1) {
    __half2 h = __floats2half2_rn(y0, y1);
    return *reinterpret_cast<uint32_t*>(&h);
}

// ---------------------------------------------------------------------------
// fp16 GEMM via mma.sync + ldmatrix: C[M,N] = alpha*(A@B^T)(*rowscale)(+bias)
//   NSEG=3: C = Ah@Bh + Al@Bh + Ah@Bl  (split)   NSEG=1: C = Ah@Bh (single)
//   A: [M,K] K-major fp16, B: [N,K] K-major fp16.
//   BM=BN=128, BK=32, 4-stage cp.async, 256 threads, warp grid 4x2,
//   warp tile 32x64. Smem rows 80B (20 banks) -> conflict-free LDSM.
//   OUT_MODE: 0 = fp32, 1 = split fp16 (outH/outL), 2 = single fp16 (outH)
// ---------------------------------------------------------------------------
constexpr int BM = 128, BN = 128, BK = 32, STAGES = 4;
constexpr int ROWB = 80;
constexpr int STAGE_B = 128 * ROWB;            // 10240 B
constexpr int SMEM_SZ = 2 * STAGES * STAGE_B;  // 81920 B

template <int NSEG, bool HAS_BIAS, bool HAS_RS, int OUT_MODE>
__global__ __launch_bounds__(256, 2) void mm_tc(
    const __half* __restrict__ Ah, const __half* __restrict__ Al,
    const __half* __restrict__ Bh, const __half* __restrict__ Bl,
    const float* __restrict__ bias, const float* __restrict__ rowscale,
    float alpha,
    float* __restrict__ outF, __half* __restrict__ outH,
    __half* __restrict__ outL, int M, int N, int K)
{
    extern __shared__ char smem[];
    const uint32_t sb = smem_u32(smem);
    const int t = threadIdx.x, wid = t >> 5, lane = t & 31;
    const int wm = wid & 3, wn = wid >> 2;
    const int g = lane >> 2, tq = lane & 3;
    const uint32_t lrow = lane & 15;
    const uint32_t lcol = (lane >> 4) * 16;
    const int rowBase = blockIdx.y * BM, colBase = blockIdx.x * BN;
    const int KC = K / BK, KT = NSEG * KC;

    const __half* aseg[NSEG];
    const __half* bseg[NSEG];
    aseg[0] = Ah; bseg[0] = Bh;
    if (NSEG == 3) { aseg[1] = Al; aseg[2] = Ah; bseg[1] = Bh; bseg[2] = Bl; }

    float acc[2][8][4];
#pragma unroll
    for (int i = 0; i < 2; i++)
#pragma unroll
        for (int j = 0; j < 8; j++)
#pragma unroll
            for (int c = 0; c < 4; c++) acc[i][j][c] = 0.f;

    auto load_chunk = [&](int kt) {
        const int stage = kt % STAGES;
        int seg = 0, kk = kt;
        if (NSEG == 3) {
            seg = (kt >= 2 * KC) ? 2 : ((kt >= KC) ? 1 : 0);
            kk = kt - seg * KC;
        }
        const size_t kOff = (size_t)kk * BK;
        const __half* As = aseg[seg];
        const __half* Bs = bseg[seg];
        const uint32_t aBase = sb + stage * STAGE_B;
        const uint32_t bBase = sb + (STAGES + stage) * STAGE_B;
#pragma unroll
        for (int i = 0; i < 2; i++) {
            const int chunk = t + i * 256;
            const int row = chunk >> 2;
            const int c16 = chunk & 3;
            const uint32_t soff = row * ROWB + c16 * 16;
            cp16(aBase + soff, As + (size_t)(rowBase + row) * K + kOff + c16 * 8);
            cp16(bBase + soff, Bs + (size_t)(colBase + row) * K + kOff + c16 * 8);
        }
        cp_commit();
    };

    for (int i = 0; i < STAGES - 1; i++) load_chunk(i);

    for (int kt = 0; kt < KT; kt++) {
        cp_wait<STAGES - 2>();
        __syncthreads();
        if (kt + STAGES - 1 < KT) load_chunk(kt + STAGES - 1);
        else cp_commit();

        const int stage = kt % STAGES;
        const uint32_t aS = sb + stage * STAGE_B;
        const uint32_t bS = sb + (STAGES + stage) * STAGE_B;

#pragma unroll
        for (int kk = 0; kk < BK; kk += 16) {
            uint32_t a[2][4];
            ldsm4(a[0], aS + (wm * 32 + 0  + lrow) * ROWB + kk * 2 + lcol);
            ldsm4(a[1], aS + (wm * 32 + 16 + lrow) * ROWB + kk * 2 + lcol);
#pragma unroll
            for (int j2 = 0; j2 < 4; j2++) {
                uint32_t b[4];
                ldsm4(b, bS + (wn * 64 + j2 * 16 + lrow) * ROWB + kk * 2 + lcol);
                mma16816(acc[0][2 * j2 + 0], a[0], b[0], b[2]);
                mma16816(acc[1][2 * j2 + 0], a[1], b[0], b[2]);
                mma16816(acc[0][2 * j2 + 1], a[0], b[1], b[3]);
                mma16816(acc[1][2 * j2 + 1], a[1], b[1], b[3]);
            }
        }
        __syncthreads();
    }

    // --- epilogue ---
#pragma unroll
    for (int i = 0; i < 2; i++) {
        const int r0 = rowBase + wm * 32 + i * 16 + g;
        float rsA = 1.f, rsB = 1.f;
        if (HAS_RS) { rsA = __ldg(rowscale + r0); rsB = __ldg(rowscale + r0 + 8); }
#pragma unroll
        for (int j = 0; j < 8; j++) {
            const int col = colBase + wn * 64 + j * 8 + 2 * tq;
            float y0 = acc[i][j][0] * alpha, y1 = acc[i][j][1] * alpha;
            float y2 = acc[i][j][2] * alpha, y3 = acc[i][j][3] * alpha;
            if (HAS_RS) { y0 *= rsA; y1 *= rsA; y2 *= rsB; y3 *= rsB; }
            if (HAS_BIAS) {
                const float b0 = __ldg(bias + col), b1 = __ldg(bias + col + 1);
                y0 += b0; y1 += b1; y2 += b0; y3 += b1;
            }
            if (OUT_MODE == 1) {
                uint32_t h, l;
                split2h(y0, y1, h, l);
                *reinterpret_cast<uint32_t*>(outH + (size_t)r0 * N + col) = h;
                *reinterpret_cast<uint32_t*>(outL + (size_t)r0 * N + col) = l;
                split2h(y2, y3, h, l);
                *reinterpret_cast<uint32_t*>(outH + (size_t)(r0 + 8) * N + col) = h;
                *reinterpret_cast<uint32_t*>(outL + (size_t)(r0 + 8) * N + col) = l;
            } else if (OUT_MODE == 2) {
                *reinterpret_cast<uint32_t*>(outH + (size_t)r0 * N + col) =
                    pack2h(y0, y1);
                *reinterpret_cast<uint32_t*>(outH + (size_t)(r0 + 8) * N + col) =
                    pack2h(y2, y3);
            } else {
                *reinterpret_cast<float2*>(outF + (size_t)r0 * N + col) =
                    make_float2(y0, y1);
                *reinterpret_cast<float2*>(outF + (size_t)(r0 + 8) * N + col) =
                    make_float2(y2, y3);
            }
        }
    }
}

// ---------------------------------------------------------------------------
// fp32 -> fp16 hi/lo elementwise
// ---------------------------------------------------------------------------
__global__ void convert_split_kernel(const float* __restrict__ in,
                                     __half* __restrict__ oh,
                                     __half* __restrict__ ol, int n4)
{
    int i = blockIdx.x * blockDim.x + threadIdx.x;
    if (i >= n4) return;
    float4 v = reinterpret_cast<const float4*>(in)[i];
    uint32_t h0, l0, h1, l1;
    split2h(v.x, v.y, h0, l0);
    split2h(v.z, v.w, h1, l1);
    reinterpret_cast<uint2*>(oh)[i] = make_uint2(h0, h1);
    reinterpret_cast<uint2*>(ol)[i] = make_uint2(l0, l1);
}

// ---------------------------------------------------------------------------
// fp32 [R,C] -> transposed fp16 hi/lo [C,R]
// ---------------------------------------------------------------------------
__global__ void transpose_split_kernel(const float* __restrict__ in,
                                       __half* __restrict__ oh,
                                       __half* __restrict__ ol,
                                       int R, int C)
{
    __shared__ float tile[32][33];
    const int cb = blockIdx.x * 32, r0 = blockIdx.y * 32;
    const int tx = threadIdx.x, ty = threadIdx.y;
#pragma unroll
    for (int i = ty; i < 32; i += 8)
        tile[i][tx] = in[(size_t)(r0 + i) * C + cb + tx];
    __syncthreads();
#pragma unroll
    for (int i = ty; i < 32; i += 8) {
        float v = tile[tx][i];
        __half h = __float2half_rn(v);
        __half l = __float2half_rn(v - __half2float(h));
        oh[(size_t)(cb + i) * R + r0 + tx] = h;
        ol[(size_t)(cb + i) * R + r0 + tx] = l;
    }
}

// ---------------------------------------------------------------------------
// fp32 [R,C] -> transposed single fp16 [C,R]
// ---------------------------------------------------------------------------
__global__ void transpose_half_kernel(const float* __restrict__ in,
                                      __half* __restrict__ out, int R, int C)
{
    __shared__ float tile[32][33];
    const int cb = blockIdx.x * 32, r0 = blockIdx.y * 32;
    const int tx = threadIdx.x, ty = threadIdx.y;
#pragma unroll
    for (int i = ty; i < 32; i += 8)
        tile[i][tx] = in[(size_t)(r0 + i) * C + cb + tx];
    __syncthreads();
#pragma unroll
    for (int i = ty; i < 32; i += 8)
        out[(size_t)(cb + i) * R + r0 + tx] = __float2half_rn(tile[tx][i]);
}

// ---------------------------------------------------------------------------
// Row softmax (unnormalized) over 4096 cols: E = exp(s - max) fp16,
// invsum[row] = 1/sum(E). One 256-thread block per row.
// ---------------------------------------------------------------------------
__global__ __launch_bounds__(256) void softmax4096_kernel(
    const float* __restrict__ S, __half* __restrict__ E,
    float* __restrict__ invsum)
{
    const float4* row = reinterpret_cast<const float4*>(S + (size_t)blockIdx.x * 4096);
    const int tid = threadIdx.x;
    __shared__ float red[8];

    float4 v[4];
    float m = -INFINITY;
#pragma unroll
    for (int s = 0; s < 4; s++) {
        v[s] = row[tid + s * 256];
        m = fmaxf(m, fmaxf(fmaxf(v[s].x, v[s].y), fmaxf(v[s].z, v[s].w)));
    }
#pragma unroll
    for (int o = 16; o; o >>= 1) m = fmaxf(m, __shfl_xor_sync(0xffffffffu, m, o));
    if ((tid & 31) == 0) red[tid >> 5] = m;
    __syncthreads();
    float mAll = red[0];
#pragma unroll
    for (int w = 1; w < 8; w++) mAll = fmaxf(mAll, red[w]);
    __syncthreads();

    float sum = 0.f;
#pragma unroll
    for (int s = 0; s < 4; s++) {
        v[s].x = __expf(v[s].x - mAll);
        v[s].y = __expf(v[s].y - mAll);
        v[s].z = __expf(v[s].z - mAll);
        v[s].w = __expf(v[s].w - mAll);
        sum += (v[s].x + v[s].y) + (v[s].z + v[s].w);
    }
#pragma unroll
    for (int o = 16; o; o >>= 1) sum += __shfl_xor_sync(0xffffffffu, sum, o);
    if ((tid & 31) == 0) red[tid >> 5] = sum;
    __syncthreads();
    float sAll = 0.f;
#pragma unroll
    for (int w = 0; w < 8; w++) sAll += red[w];
    if (tid == 0) invsum[blockIdx.x] = 1.f / sAll;

    uint2* oe = reinterpret_cast<uint2*>(E + (size_t)blockIdx.x * 4096);
#pragma unroll
    for (int s = 0; s < 4; s++)
        oe[tid + s * 256] =
            make_uint2(pack2h(v[s].x, v[s].y), pack2h(v[s].z, v[s].w));
}

// ---------------------------------------------------------------------------
// Launch
// ---------------------------------------------------------------------------
extern "C" void kernel_launch(void* const* d_in, const int* in_sizes, int n_in,
                              void* d_out, int out_size)
{
    const float* me = (const float*)d_in[0];
    const float* ce = (const float*)d_in[1];
    const float* Wq = (const float*)d_in[2];
    const float* bq = (const float*)d_in[3];
    const float* Wk = (const float*)d_in[4];
    const float* bk = (const float*)d_in[5];
    const float* Wv = (const float*)d_in[6];
    const float* bv = (const float*)d_in[7];
    const float* Wo = (const float*)d_in[8];
    const float* bo = (const float*)d_in[9];
    float* out = (float*)d_out;

    cudaFuncSetAttribute(mm_tc<3, true,  false, 2>, cudaFuncAttributeMaxDynamicSharedMemorySize, SMEM_SZ);
    cudaFuncSetAttribute(mm_tc<3, true,  false, 0>, cudaFuncAttributeMaxDynamicSharedMemorySize, SMEM_SZ);
    cudaFuncSetAttribute(mm_tc<1, false, false, 0>, cudaFuncAttributeMaxDynamicSharedMemorySize, SMEM_SZ);
    cudaFuncSetAttribute(mm_tc<1, false, true,  1>, cudaFuncAttributeMaxDynamicSharedMemorySize, SMEM_SZ);

    __half *me_h, *me_l, *ce_h, *ce_l, *wqt_h, *wqt_l, *wkt_h, *wkt_l;
    __half *wvt_h, *wvt_l, *wot_h, *wot_l, *q, *k, *vt, *e, *x_h, *x_l;
    float *v, *s, *invsum;
    cudaGetSymbolAddress((void**)&me_h, g_me_h);  cudaGetSymbolAddress((void**)&me_l, g_me_l);
    cudaGetSymbolAddress((void**)&ce_h, g_ce_h);  cudaGetSymbolAddress((void**)&ce_l, g_ce_l);
    cudaGetSymbolAddress((void**)&wqt_h, g_wqt_h); cudaGetSymbolAddress((void**)&wqt_l, g_wqt_l);
    cudaGetSymbolAddress((void**)&wkt_h, g_wkt_h); cudaGetSymbolAddress((void**)&wkt_l, g_wkt_l);
    cudaGetSymbolAddress((void**)&wvt_h, g_wvt_h); cudaGetSymbolAddress((void**)&wvt_l, g_wvt_l);
    cudaGetSymbolAddress((void**)&wot_h, g_wot_h); cudaGetSymbolAddress((void**)&wot_l, g_wot_l);
    cudaGetSymbolAddress((void**)&q, g_q);
    cudaGetSymbolAddress((void**)&k, g_k);
    cudaGetSymbolAddress((void**)&v, g_v);
    cudaGetSymbolAddress((void**)&vt, g_vt);
    cudaGetSymbolAddress((void**)&s, g_s);
    cudaGetSymbolAddress((void**)&e, g_e);
    cudaGetSymbolAddress((void**)&invsum, g_invsum);
    cudaGetSymbolAddress((void**)&x_h, g_x_h);    cudaGetSymbolAddress((void**)&x_l, g_x_l);

    const int MQ = 16384, Cn = 4096, Ad = 512, Dd = 512, Pd = 512;
    const float scale = 0.044194173824159216f;  // 1/sqrt(512)

    convert_split_kernel<<<(MQ * Dd / 4 + 255) / 256, 256>>>(me, me_h, me_l, MQ * Dd / 4);
    convert_split_kernel<<<(Cn * Dd / 4 + 255) / 256, 256>>>(ce, ce_h, ce_l, Cn * Dd / 4);
    dim3 tb(32, 8);
    transpose_split_kernel<<<dim3(16, 16), tb>>>(Wq, wqt_h, wqt_l, Dd, Ad);
    transpose_split_kernel<<<dim3(16, 16), tb>>>(Wk, wkt_h, wkt_l, Dd, Ad);
    transpose_split_kernel<<<dim3(16, 16), tb>>>(Wv, wvt_h, wvt_l, Dd, Ad);
    transpose_split_kernel<<<dim3(16, 16), tb>>>(Wo, wot_h, wot_l, Ad, Pd);

    // q = ME @ Wq + bq  -> single fp16 (3-term split GEMM)
    mm_tc<3, true, false, 2><<<dim3(Ad / BN, MQ / BM), 256, SMEM_SZ>>>(
        me_h, me_l, wqt_h, wqt_l, bq, nullptr, 1.f, nullptr, q, nullptr, MQ, Ad, Dd);
    // k = CE @ Wk + bk  -> single fp16
    mm_tc<3, true, false, 2><<<dim3(Ad / BN, Cn / BM), 256, SMEM_SZ>>>(
        ce_h, ce_l, wkt_h, wkt_l, bk, nullptr, 1.f, nullptr, k, nullptr, Cn, Ad, Dd);
    // v = CE @ Wv + bv  -> fp32
    mm_tc<3, true, false, 0><<<dim3(Ad / BN, Cn / BM), 256, SMEM_SZ>>>(
        ce_h, ce_l, wvt_h, wvt_l, bv, nullptr, 1.f, v, nullptr, nullptr, Cn, Ad, Dd);
    // vt = v^T -> single fp16
    transpose_half_kernel<<<dim3(Ad / 32, Cn / 32), tb>>>(v, vt, Cn, Ad);
    // s = scale * q @ k^T -> fp32 (single-pass fp16)
    mm_tc<1, false, false, 0><<<dim3(Cn / BN, MQ / BM), 256, SMEM_SZ>>>(
        q, nullptr, k, nullptr, nullptr, nullptr, scale, s, nullptr, nullptr, MQ, Cn, Ad);
    // e = exp(s - max), invsum
    softmax4096_kernel<<<MQ, 256>>>(s, e, invsum);
    // x = (e @ vt^T) * invsum -> split fp16 (single-pass fp16 GEMM)
    mm_tc<1, false, true, 1><<<dim3(Ad / BN, MQ / BM), 256, SMEM_SZ>>>(
        e, nullptr, vt, nullptr, nullptr, invsum, 1.f, nullptr, x_h, x_l, MQ, Ad, Cn);
    // out = x @ Wo + bo -> fp32 (3-term split)
    mm_tc<3, true, false, 0><<<dim3(Pd / BN, MQ / BM), 256, SMEM_SZ>>>(
        x_h, x_l, wot_h, wot_l, bo, nullptr, 1.f, out, nullptr, nullptr, MQ, Pd, Ad);
}

// round 6
// speedup vs baseline: 5.0132x; 1.1419x over previous
#include <cuda_runtime.h>
#include <cuda_fp16.h>
#include <math.h>
#include <stdint.h>

// B=16, T=1024 (MQ=16384), D=512, C=4096, DC=512, A=512, P=512
//
// mma.sync fp16 (fp32 accum). q/k/v projections + scores + PV run single-pass
// fp16 (downstream fp16 rounding dominates anyway). Output projection keeps a
// 3-term hi/lo split (its error is unsmoothed). Softmax emits unnormalized
// exp in fp16 + inv_sum; the PV epilogue normalizes.

#define DINL __device__ __forceinline__

// ---------------------------------------------------------------------------
// Scratch
// ---------------------------------------------------------------------------
__device__ __align__(256) __half g_me[16384 * 512];
__device__ __align__(256) __half g_ce[4096 * 512];
__device__ __align__(256) __half g_wqt[512 * 512];
__device__ __align__(256) __half g_wkt[512 * 512];
__device__ __align__(256) __half g_wvt[512 * 512];
__device__ __align__(256) __half g_wot_h[512 * 512], g_wot_l[512 * 512];
__device__ __align__(256) __half g_q[16384 * 512];
__device__ __align__(256) __half g_k[4096 * 512];
__device__ __align__(256) float  g_v[4096 * 512];
__device__ __align__(256) __half g_vt[512 * 4096];
__device__ __align__(256) float  g_s[(size_t)16384 * 4096];
__device__ __align__(256) __half g_e[(size_t)16384 * 4096];
__device__ __align__(256) float  g_invsum[16384];
__device__ __align__(256) __half g_x_h[16384 * 512], g_x_l[16384 * 512];

// ---------------------------------------------------------------------------
// Helpers
// ---------------------------------------------------------------------------
DINL uint32_t smem_u32(const void* p) {
    uint32_t a;
    asm("{ .reg .u64 t; cvta.to.shared.u64 t, %1; cvt.u32.u64 %0, t; }"
        : "=r"(a) : "l"(p));
    return a;
}
DINL void cp16(uint32_t dst, const void* src) {
    asm volatile("cp.async.cg.shared.global [%0], [%1], 16;"
                 :: "r"(dst), "l"(src) : "memory");
}
DINL void cp_commit() { asm volatile("cp.async.commit_group;" ::: "memory"); }
template <int N> DINL void cp_wait() {
    asm volatile("cp.async.wait_group %0;" :: "n"(N) : "memory");
}
DINL void ldsm4(uint32_t* r, uint32_t addr) {
    asm volatile("ldmatrix.sync.aligned.m8n8.x4.shared.b16 {%0,%1,%2,%3}, [%4];"
                 : "=r"(r[0]), "=r"(r[1]), "=r"(r[2]), "=r"(r[3]) : "r"(addr));
}
DINL void mma16816(float* c, const uint32_t* a, uint32_t b0, uint32_t b1) {
    asm volatile(
        "mma.sync.aligned.m16n8k16.row.col.f32.f16.f16.f32 "
        "{%0,%1,%2,%3}, {%4,%5,%6,%7}, {%8,%9}, {%0,%1,%2,%3};"
        : "+f"(c[0]), "+f"(c[1]), "+f"(c[2]), "+f"(c[3])
        : "r"(a[0]), "r"(a[1]), "r"(a[2]), "r"(a[3]), "r"(b0), "r"(b1));
}
DINL void split2h(float y0, float y1, uint32_t& h2, uint32_t& l2) {
    __half2 h = __floats2half2_rn(y0, y1);
    float r0 = y0 - __low2float(h);
    float r1 = y1 - __high2float(h);
    __half2 l = __floats2half2_rn(r0, r1);
    h2 = *reinterpret_cast<uint32_t*>(&h);
    l2 = *reinterpret_cast<uint32_t*>(&l);
}
DINL uint32_t pack2h(float y0, float y1) {
    __half2 h = __floats2half2_rn(y0, y1);
    return *reinterpret_cast<uint32_t*>(&h);
}

// ---------------------------------------------------------------------------
// fp16 GEMM via mma.sync + ldmatrix: C[M,N] = alpha*(A@B^T)(*rowscale)(+bias)
//   NSEG=3: C = Ah@Bh + Al@Bh + Ah@Bl    NSEG=1: C = Ah@Bh
//   A: [M,K] K-major fp16, B: [N,K] K-major fp16.
//   BM=BN=128, BK=32, 4-stage cp.async, 256 threads, warp grid 4x2,
//   warp tile 32x64. Smem rows 80B (20 banks) -> conflict-free LDSM.
//   OUT_MODE: 0 = fp32, 1 = split fp16 (outH/outL), 2 = single fp16 (outH)
// ---------------------------------------------------------------------------
constexpr int BM = 128, BN = 128, BK = 32, STAGES = 4;
constexpr int ROWB = 80;
constexpr int STAGE_B = 128 * ROWB;            // 10240 B
constexpr int SMEM_SZ = 2 * STAGES * STAGE_B;  // 81920 B

template <int NSEG, bool HAS_BIAS, bool HAS_RS, int OUT_MODE>
__global__ __launch_bounds__(256, 2) void mm_tc(
    const __half* __restrict__ Ah, const __half* __restrict__ Al,
    const __half* __restrict__ Bh, const __half* __restrict__ Bl,
    const float* __restrict__ bias, const float* __restrict__ rowscale,
    float alpha,
    float* __restrict__ outF, __half* __restrict__ outH,
    __half* __restrict__ outL, int M, int N, int K)
{
    extern __shared__ char smem[];
    const uint32_t sb = smem_u32(smem);
    const int t = threadIdx.x, wid = t >> 5, lane = t & 31;
    const int wm = wid & 3, wn = wid >> 2;
    const int g = lane >> 2, tq = lane & 3;
    const uint32_t lrow = lane & 15;
    const uint32_t lcol = (lane >> 4) * 16;
    const int rowBase = blockIdx.y * BM, colBase = blockIdx.x * BN;
    const int KC = K / BK, KT = NSEG * KC;

    const __half* aseg[NSEG];
    const __half* bseg[NSEG];
    aseg[0] = Ah; bseg[0] = Bh;
    if (NSEG == 3) { aseg[1] = Al; aseg[2] = Ah; bseg[1] = Bh; bseg[2] = Bl; }

    float acc[2][8][4];
#pragma unroll
    for (int i = 0; i < 2; i++)
#pragma unroll
        for (int j = 0; j < 8; j++)
#pragma unroll
            for (int c = 0; c < 4; c++) acc[i][j][c] = 0.f;

    auto load_chunk = [&](int kt) {
        const int stage = kt % STAGES;
        int seg = 0, kk = kt;
        if (NSEG == 3) {
            seg = (kt >= 2 * KC) ? 2 : ((kt >= KC) ? 1 : 0);
            kk = kt - seg * KC;
        }
        const size_t kOff = (size_t)kk * BK;
        const __half* As = aseg[seg];
        const __half* Bs = bseg[seg];
        const uint32_t aBase = sb + stage * STAGE_B;
        const uint32_t bBase = sb + (STAGES + stage) * STAGE_B;
#pragma unroll
        for (int i = 0; i < 2; i++) {
            const int chunk = t + i * 256;
            const int row = chunk >> 2;
            const int c16 = chunk & 3;
            const uint32_t soff = row * ROWB + c16 * 16;
            cp16(aBase + soff, As + (size_t)(rowBase + row) * K + kOff + c16 * 8);
            cp16(bBase + soff, Bs + (size_t)(colBase + row) * K + kOff + c16 * 8);
        }
        cp_commit();
    };

    for (int i = 0; i < STAGES - 1; i++) load_chunk(i);

    for (int kt = 0; kt < KT; kt++) {
        cp_wait<STAGES - 2>();
        __syncthreads();
        if (kt + STAGES - 1 < KT) load_chunk(kt + STAGES - 1);
        else cp_commit();

        const int stage = kt % STAGES;
        const uint32_t aS = sb + stage * STAGE_B;
        const uint32_t bS = sb + (STAGES + stage) * STAGE_B;

#pragma unroll
        for (int kk = 0; kk < BK; kk += 16) {
            uint32_t a[2][4];
            ldsm4(a[0], aS + (wm * 32 + 0  + lrow) * ROWB + kk * 2 + lcol);
            ldsm4(a[1], aS + (wm * 32 + 16 + lrow) * ROWB + kk * 2 + lcol);
#pragma unroll
            for (int j2 = 0; j2 < 4; j2++) {
                uint32_t b[4];
                ldsm4(b, bS + (wn * 64 + j2 * 16 + lrow) * ROWB + kk * 2 + lcol);
                mma16816(acc[0][2 * j2 + 0], a[0], b[0], b[2]);
                mma16816(acc[1][2 * j2 + 0], a[1], b[0], b[2]);
                mma16816(acc[0][2 * j2 + 1], a[0], b[1], b[3]);
                mma16816(acc[1][2 * j2 + 1], a[1], b[1], b[3]);
            }
        }
        __syncthreads();
    }

    // --- epilogue ---
#pragma unroll
    for (int i = 0; i < 2; i++) {
        const int r0 = rowBase + wm * 32 + i * 16 + g;
        float rsA = 1.f, rsB = 1.f;
        if (HAS_RS) { rsA = __ldg(rowscale + r0); rsB = __ldg(rowscale + r0 + 8); }
#pragma unroll
        for (int j = 0; j < 8; j++) {
            const int col = colBase + wn * 64 + j * 8 + 2 * tq;
            float y0 = acc[i][j][0] * alpha, y1 = acc[i][j][1] * alpha;
            float y2 = acc[i][j][2] * alpha, y3 = acc[i][j][3] * alpha;
            if (HAS_RS) { y0 *= rsA; y1 *= rsA; y2 *= rsB; y3 *= rsB; }
            if (HAS_BIAS) {
                const float b0 = __ldg(bias + col), b1 = __ldg(bias + col + 1);
                y0 += b0; y1 += b1; y2 += b0; y3 += b1;
            }
            if (OUT_MODE == 1) {
                uint32_t h, l;
                split2h(y0, y1, h, l);
                *reinterpret_cast<uint32_t*>(outH + (size_t)r0 * N + col) = h;
                *reinterpret_cast<uint32_t*>(outL + (size_t)r0 * N + col) = l;
                split2h(y2, y3, h, l);
                *reinterpret_cast<uint32_t*>(outH + (size_t)(r0 + 8) * N + col) = h;
                *reinterpret_cast<uint32_t*>(outL + (size_t)(r0 + 8) * N + col) = l;
            } else if (OUT_MODE == 2) {
                *reinterpret_cast<uint32_t*>(outH + (size_t)r0 * N + col) =
                    pack2h(y0, y1);
                *reinterpret_cast<uint32_t*>(outH + (size_t)(r0 + 8) * N + col) =
                    pack2h(y2, y3);
            } else {
                *reinterpret_cast<float2*>(outF + (size_t)r0 * N + col) =
                    make_float2(y0, y1);
                *reinterpret_cast<float2*>(outF + (size_t)(r0 + 8) * N + col) =
                    make_float2(y2, y3);
            }
        }
    }
}

// ---------------------------------------------------------------------------
// fp32 -> fp16 elementwise
// ---------------------------------------------------------------------------
__global__ void convert_half_kernel(const float* __restrict__ in,
                                    __half* __restrict__ o, int n4)
{
    int i = blockIdx.x * blockDim.x + threadIdx.x;
    if (i >= n4) return;
    float4 v = reinterpret_cast<const float4*>(in)[i];
    reinterpret_cast<uint2*>(o)[i] =
        make_uint2(pack2h(v.x, v.y), pack2h(v.z, v.w));
}

// ---------------------------------------------------------------------------
// fp32 [R,C] -> transposed fp16 [C,R]
// ---------------------------------------------------------------------------
__global__ void transpose_half_kernel(const float* __restrict__ in,
                                      __half* __restrict__ out, int R, int C)
{
    __shared__ float tile[32][33];
    const int cb = blockIdx.x * 32, r0 = blockIdx.y * 32;
    const int tx = threadIdx.x, ty = threadIdx.y;
#pragma unroll
    for (int i = ty; i < 32; i += 8)
        tile[i][tx] = in[(size_t)(r0 + i) * C + cb + tx];
    __syncthreads();
#pragma unroll
    for (int i = ty; i < 32; i += 8)
        out[(size_t)(cb + i) * R + r0 + tx] = __float2half_rn(tile[tx][i]);
}

// ---------------------------------------------------------------------------
// fp32 [R,C] -> transposed fp16 hi/lo [C,R]  (for Wo split)
// ---------------------------------------------------------------------------
__global__ void transpose_split_kernel(const float* __restrict__ in,
                                       __half* __restrict__ oh,
                                       __half* __restrict__ ol,
                                       int R, int C)
{
    __shared__ float tile[32][33];
    const int cb = blockIdx.x * 32, r0 = blockIdx.y * 32;
    const int tx = threadIdx.x, ty = threadIdx.y;
#pragma unroll
    for (int i = ty; i < 32; i += 8)
        tile[i][tx] = in[(size_t)(r0 + i) * C + cb + tx];
    __syncthreads();
#pragma unroll
    for (int i = ty; i < 32; i += 8) {
        float v = tile[tx][i];
        __half h = __float2half_rn(v);
        __half l = __float2half_rn(v - __half2float(h));
        oh[(size_t)(cb + i) * R + r0 + tx] = h;
        ol[(size_t)(cb + i) * R + r0 + tx] = l;
    }
}

// ---------------------------------------------------------------------------
// Row softmax (unnormalized): E = exp(s - max) fp16, invsum = 1/sum(E).
// ---------------------------------------------------------------------------
__global__ __launch_bounds__(256) void softmax4096_kernel(
    const float* __restrict__ S, __half* __restrict__ E,
    float* __restrict__ invsum)
{
    const float4* row = reinterpret_cast<const float4*>(S + (size_t)blockIdx.x * 4096);
    const int tid = threadIdx.x;
    __shared__ float red[8];

    float4 v[4];
    float m = -INFINITY;
#pragma unroll
    for (int s = 0; s < 4; s++) {
        v[s] = row[tid + s * 256];
        m = fmaxf(m, fmaxf(fmaxf(v[s].x, v[s].y), fmaxf(v[s].z, v[s].w)));
    }
#pragma unroll
    for (int o = 16; o; o >>= 1) m = fmaxf(m, __shfl_xor_sync(0xffffffffu, m, o));
    if ((tid & 31) == 0) red[tid >> 5] = m;
    __syncthreads();
    float mAll = red[0];
#pragma unroll
    for (int w = 1; w < 8; w++) mAll = fmaxf(mAll, red[w]);
    __syncthreads();

    float sum = 0.f;
#pragma unroll
    for (int s = 0; s < 4; s++) {
        v[s].x = __expf(v[s].x - mAll);
        v[s].y = __expf(v[s].y - mAll);
        v[s].z = __expf(v[s].z - mAll);
        v[s].w = __expf(v[s].w - mAll);
        sum += (v[s].x + v[s].y) + (v[s].z + v[s].w);
    }
#pragma unroll
    for (int o = 16; o; o >>= 1) sum += __shfl_xor_sync(0xffffffffu, sum, o);
    if ((tid & 31) == 0) red[tid >> 5] = sum;
    __syncthreads();
    float sAll = 0.f;
#pragma unroll
    for (int w = 0; w < 8; w++) sAll += red[w];
    if (tid == 0) invsum[blockIdx.x] = 1.f / sAll;

    uint2* oe = reinterpret_cast<uint2*>(E + (size_t)blockIdx.x * 4096);
#pragma unroll
    for (int s = 0; s < 4; s++)
        oe[tid + s * 256] =
            make_uint2(pack2h(v[s].x, v[s].y), pack2h(v[s].z, v[s].w));
}

// ---------------------------------------------------------------------------
// Launch
// ---------------------------------------------------------------------------
extern "C" void kernel_launch(void* const* d_in, const int* in_sizes, int n_in,
                              void* d_out, int out_size)
{
    const float* me = (const float*)d_in[0];
    const float* ce = (const float*)d_in[1];
    const float* Wq = (const float*)d_in[2];
    const float* bq = (const float*)d_in[3];
    const float* Wk = (const float*)d_in[4];
    const float* bk = (const float*)d_in[5];
    const float* Wv = (const float*)d_in[6];
    const float* bv = (const float*)d_in[7];
    const float* Wo = (const float*)d_in[8];
    const float* bo = (const float*)d_in[9];
    float* out = (float*)d_out;

    cudaFuncSetAttribute(mm_tc<1, true,  false, 2>, cudaFuncAttributeMaxDynamicSharedMemorySize, SMEM_SZ);
    cudaFuncSetAttribute(mm_tc<1, true,  false, 0>, cudaFuncAttributeMaxDynamicSharedMemorySize, SMEM_SZ);
    cudaFuncSetAttribute(mm_tc<1, false, false, 0>, cudaFuncAttributeMaxDynamicSharedMemorySize, SMEM_SZ);
    cudaFuncSetAttribute(mm_tc<1, false, true,  1>, cudaFuncAttributeMaxDynamicSharedMemorySize, SMEM_SZ);
    cudaFuncSetAttribute(mm_tc<3, true,  false, 0>, cudaFuncAttributeMaxDynamicSharedMemorySize, SMEM_SZ);

    __half *meH, *ceH, *wqt, *wkt, *wvt, *wot_h, *wot_l, *q, *k, *vt, *e, *x_h, *x_l;
    float *v, *s, *invsum;
    cudaGetSymbolAddress((void**)&meH, g_me);
    cudaGetSymbolAddress((void**)&ceH, g_ce);
    cudaGetSymbolAddress((void**)&wqt, g_wqt);
    cudaGetSymbolAddress((void**)&wkt, g_wkt);
    cudaGetSymbolAddress((void**)&wvt, g_wvt);
    cudaGetSymbolAddress((void**)&wot_h, g_wot_h); cudaGetSymbolAddress((void**)&wot_l, g_wot_l);
    cudaGetSymbolAddress((void**)&q, g_q);
    cudaGetSymbolAddress((void**)&k, g_k);
    cudaGetSymbolAddress((void**)&v, g_v);
    cudaGetSymbolAddress((void**)&vt, g_vt);
    cudaGetSymbolAddress((void**)&s, g_s);
    cudaGetSymbolAddress((void**)&e, g_e);
    cudaGetSymbolAddress((void**)&invsum, g_invsum);
    cudaGetSymbolAddress((void**)&x_h, g_x_h);    cudaGetSymbolAddress((void**)&x_l, g_x_l);

    const int MQ = 16384, Cn = 4096, Ad = 512, Dd = 512, Pd = 512;
    const float scale = 0.044194173824159216f;  // 1/sqrt(512)

    convert_half_kernel<<<(MQ * Dd / 4 + 255) / 256, 256>>>(me, meH, MQ * Dd / 4);
    convert_half_kernel<<<(Cn * Dd / 4 + 255) / 256, 256>>>(ce, ceH, Cn * Dd / 4);
    dim3 tb(32, 8);
    transpose_half_kernel<<<dim3(16, 16), tb>>>(Wq, wqt, Dd, Ad);
    transpose_half_kernel<<<dim3(16, 16), tb>>>(Wk, wkt, Dd, Ad);
    transpose_half_kernel<<<dim3(16, 16), tb>>>(Wv, wvt, Dd, Ad);
    transpose_split_kernel<<<dim3(16, 16), tb>>>(Wo, wot_h, wot_l, Ad, Pd);

    // q = ME @ Wq + bq  -> fp16 (single-pass)
    mm_tc<1, true, false, 2><<<dim3(Ad / BN, MQ / BM), 256, SMEM_SZ>>>(
        meH, nullptr, wqt, nullptr, bq, nullptr, 1.f, nullptr, q, nullptr, MQ, Ad, Dd);
    // k = CE @ Wk + bk  -> fp16
    mm_tc<1, true, false, 2><<<dim3(Ad / BN, Cn / BM), 256, SMEM_SZ>>>(
        ceH, nullptr, wkt, nullptr, bk, nullptr, 1.f, nullptr, k, nullptr, Cn, Ad, Dd);
    // v = CE @ Wv + bv  -> fp32
    mm_tc<1, true, false, 0><<<dim3(Ad / BN, Cn / BM), 256, SMEM_SZ>>>(
        ceH, nullptr, wvt, nullptr, bv, nullptr, 1.f, v, nullptr, nullptr, Cn, Ad, Dd);
    // vt = v^T -> fp16
    transpose_half_kernel<<<dim3(Ad / 32, Cn / 32), tb>>>(v, vt, Cn, Ad);
    // s = scale * q @ k^T -> fp32
    mm_tc<1, false, false, 0><<<dim3(Cn / BN, MQ / BM), 256, SMEM_SZ>>>(
        q, nullptr, k, nullptr, nullptr, nullptr, scale, s, nullptr, nullptr, MQ, Cn, Ad);
    // e = exp(s - max), invsum
    softmax4096_kernel<<<MQ, 256>>>(s, e, invsum);
    // x = (e @ vt^T) * invsum -> split fp16
    mm_tc<1, false, true, 1><<<dim3(Ad / BN, MQ / BM), 256, SMEM_SZ>>>(
        e, nullptr, vt, nullptr, nullptr, invsum, 1.f, nullptr, x_h, x_l, MQ, Ad, Cn);
    // out = x @ Wo + bo -> fp32 (3-term split: exact in x and Wo)
    mm_tc<3, true, false, 0><<<dim3(Pd / BN, MQ / BM), 256, SMEM_SZ>>>(
        x_h, x_l, wot_h, wot_l, bo, nullptr, 1.f, out, nullptr, nullptr, MQ, Pd, Ad);
}

// round 7
// speedup vs baseline: 5.7026x; 1.1375x over previous
#include <cuda_runtime.h>
#include <cuda_fp16.h>
#include <math.h>
#include <stdint.h>

// B=16, T=1024 (MQ=16384), D=512, C=4096, DC=512, A=512, P=512
//
// All GEMMs single-pass fp16 mma.sync (fp32 accum). Softmax emits
// unnormalized exp fp16 + inv_sum; PV epilogue normalizes. Scores stored fp16.
// Launch order puts the scores GEMM at launch index 5 for ncu (-s 5 -c 1).

#define DINL __device__ __forceinline__

// ---------------------------------------------------------------------------
// Scratch
// ---------------------------------------------------------------------------
__device__ __align__(256) __half g_me[16384 * 512];
__device__ __align__(256) __half g_ce[4096 * 512];
__device__ __align__(256) __half g_wqt[512 * 512];
__device__ __align__(256) __half g_wkt[512 * 512];
__device__ __align__(256) __half g_wvt[512 * 512];
__device__ __align__(256) __half g_wot[512 * 512];
__device__ __align__(256) __half g_q[16384 * 512];
__device__ __align__(256) __half g_k[4096 * 512];
__device__ __align__(256) float  g_v[4096 * 512];
__device__ __align__(256) __half g_vt[512 * 4096];
__device__ __align__(256) __half g_s[(size_t)16384 * 4096];
__device__ __align__(256) __half g_e[(size_t)16384 * 4096];
__device__ __align__(256) float  g_invsum[16384];
__device__ __align__(256) __half g_x[16384 * 512];

// ---------------------------------------------------------------------------
// Helpers
// ---------------------------------------------------------------------------
DINL uint32_t smem_u32(const void* p) {
    uint32_t a;
    asm("{ .reg .u64 t; cvta.to.shared.u64 t, %1; cvt.u32.u64 %0, t; }"
        : "=r"(a) : "l"(p));
    return a;
}
DINL void cp16(uint32_t dst, const void* src) {
    asm volatile("cp.async.cg.shared.global [%0], [%1], 16;"
                 :: "r"(dst), "l"(src) : "memory");
}
DINL void cp_commit() { asm volatile("cp.async.commit_group;" ::: "memory"); }
template <int N> DINL void cp_wait() {
    asm volatile("cp.async.wait_group %0;" :: "n"(N) : "memory");
}
DINL void ldsm4(uint32_t* r, uint32_t addr) {
    asm volatile("ldmatrix.sync.aligned.m8n8.x4.shared.b16 {%0,%1,%2,%3}, [%4];"
                 : "=r"(r[0]), "=r"(r[1]), "=r"(r[2]), "=r"(r[3]) : "r"(addr));
}
DINL void mma16816(float* c, const uint32_t* a, uint32_t b0, uint32_t b1) {
    asm volatile(
        "mma.sync.aligned.m16n8k16.row.col.f32.f16.f16.f32 "
        "{%0,%1,%2,%3}, {%4,%5,%6,%7}, {%8,%9}, {%0,%1,%2,%3};"
        : "+f"(c[0]), "+f"(c[1]), "+f"(c[2]), "+f"(c[3])
        : "r"(a[0]), "r"(a[1]), "r"(a[2]), "r"(a[3]), "r"(b0), "r"(b1));
}
DINL uint32_t pack2h(float y0, float y1) {
    __half2 h = __floats2half2_rn(y0, y1);
    return *reinterpret_cast<uint32_t*>(&h);
}

// ---------------------------------------------------------------------------
// fp16 GEMM via mma.sync + ldmatrix: C[M,N] = alpha*(A@B^T)(*rowscale)(+bias)
//   A: [M,K] K-major fp16, B: [N,K] K-major fp16.
//   BM=BN=128, BK=32, 4-stage cp.async, 256 threads, warp grid 4x2,
//   warp tile 32x64. Smem rows 80B (20 banks) -> conflict-free LDSM.
//   OUT_MODE: 0 = fp32, 2 = fp16
// ---------------------------------------------------------------------------
constexpr int BM = 128, BN = 128, BK = 32, STAGES = 4;
constexpr int ROWB = 80;
constexpr int STAGE_B = 128 * ROWB;            // 10240 B
constexpr int SMEM_SZ = 2 * STAGES * STAGE_B;  // 81920 B

template <bool HAS_BIAS, bool HAS_RS, int OUT_MODE>
__global__ __launch_bounds__(256, 2) void mm_tc(
    const __half* __restrict__ A, const __half* __restrict__ B,
    const float* __restrict__ bias, const float* __restrict__ rowscale,
    float alpha, float* __restrict__ outF, __half* __restrict__ outH,
    int M, int N, int K)
{
    extern __shared__ char smem[];
    const uint32_t sb = smem_u32(smem);
    const int t = threadIdx.x, wid = t >> 5, lane = t & 31;
    const int wm = wid & 3, wn = wid >> 2;
    const int g = lane >> 2, tq = lane & 3;
    const uint32_t lrow = lane & 15;
    const uint32_t lcol = (lane >> 4) * 16;
    const int rowBase = blockIdx.y * BM, colBase = blockIdx.x * BN;
    const int KT = K / BK;

    float acc[2][8][4];
#pragma unroll
    for (int i = 0; i < 2; i++)
#pragma unroll
        for (int j = 0; j < 8; j++)
#pragma unroll
            for (int c = 0; c < 4; c++) acc[i][j][c] = 0.f;

    auto load_chunk = [&](int kt) {
        const int stage = kt % STAGES;
        const size_t kOff = (size_t)kt * BK;
        const uint32_t aBase = sb + stage * STAGE_B;
        const uint32_t bBase = sb + (STAGES + stage) * STAGE_B;
#pragma unroll
        for (int i = 0; i < 2; i++) {
            const int chunk = t + i * 256;
            const int row = chunk >> 2;
            const int c16 = chunk & 3;
            const uint32_t soff = row * ROWB + c16 * 16;
            cp16(aBase + soff, A + (size_t)(rowBase + row) * K + kOff + c16 * 8);
            cp16(bBase + soff, B + (size_t)(colBase + row) * K + kOff + c16 * 8);
        }
        cp_commit();
    };

    for (int i = 0; i < STAGES - 1; i++) load_chunk(i);

    for (int kt = 0; kt < KT; kt++) {
        cp_wait<STAGES - 2>();
        __syncthreads();
        if (kt + STAGES - 1 < KT) load_chunk(kt + STAGES - 1);
        else cp_commit();

        const int stage = kt % STAGES;
        const uint32_t aS = sb + stage * STAGE_B;
        const uint32_t bS = sb + (STAGES + stage) * STAGE_B;

#pragma unroll
        for (int kk = 0; kk < BK; kk += 16) {
            uint32_t a[2][4];
            ldsm4(a[0], aS + (wm * 32 + 0  + lrow) * ROWB + kk * 2 + lcol);
            ldsm4(a[1], aS + (wm * 32 + 16 + lrow) * ROWB + kk * 2 + lcol);
#pragma unroll
            for (int j2 = 0; j2 < 4; j2++) {
                uint32_t b[4];
                ldsm4(b, bS + (wn * 64 + j2 * 16 + lrow) * ROWB + kk * 2 + lcol);
                mma16816(acc[0][2 * j2 + 0], a[0], b[0], b[2]);
                mma16816(acc[1][2 * j2 + 0], a[1], b[0], b[2]);
                mma16816(acc[0][2 * j2 + 1], a[0], b[1], b[3]);
                mma16816(acc[1][2 * j2 + 1], a[1], b[1], b[3]);
            }
        }
        __syncthreads();
    }

    // --- epilogue ---
#pragma unroll
    for (int i = 0; i < 2; i++) {
        const int r0 = rowBase + wm * 32 + i * 16 + g;
        float rsA = 1.f, rsB = 1.f;
        if (HAS_RS) { rsA = __ldg(rowscale + r0); rsB = __ldg(rowscale + r0 + 8); }
#pragma unroll
        for (int j = 0; j < 8; j++) {
            const int col = colBase + wn * 64 + j * 8 + 2 * tq;
            float y0 = acc[i][j][0] * alpha, y1 = acc[i][j][1] * alpha;
            float y2 = acc[i][j][2] * alpha, y3 = acc[i][j][3] * alpha;
            if (HAS_RS) { y0 *= rsA; y1 *= rsA; y2 *= rsB; y3 *= rsB; }
            if (HAS_BIAS) {
                const float b0 = __ldg(bias + col), b1 = __ldg(bias + col + 1);
                y0 += b0; y1 += b1; y2 += b0; y3 += b1;
            }
            if (OUT_MODE == 2) {
                *reinterpret_cast<uint32_t*>(outH + (size_t)r0 * N + col) =
                    pack2h(y0, y1);
                *reinterpret_cast<uint32_t*>(outH + (size_t)(r0 + 8) * N + col) =
                    pack2h(y2, y3);
            } else {
                *reinterpret_cast<float2*>(outF + (size_t)r0 * N + col) =
                    make_float2(y0, y1);
                *reinterpret_cast<float2*>(outF + (size_t)(r0 + 8) * N + col) =
                    make_float2(y2, y3);
            }
        }
    }
}

// ---------------------------------------------------------------------------
// fp32 -> fp16 elementwise
// ---------------------------------------------------------------------------
__global__ void convert_half_kernel(const float* __restrict__ in,
                                    __half* __restrict__ o, int n4)
{
    int i = blockIdx.x * blockDim.x + threadIdx.x;
    if (i >= n4) return;
    float4 v = reinterpret_cast<const float4*>(in)[i];
    reinterpret_cast<uint2*>(o)[i] =
        make_uint2(pack2h(v.x, v.y), pack2h(v.z, v.w));
}

// ---------------------------------------------------------------------------
// fp32 [R,C] -> transposed fp16 [C,R]
// ---------------------------------------------------------------------------
__global__ void transpose_half_kernel(const float* __restrict__ in,
                                      __half* __restrict__ out, int R, int C)
{
    __shared__ float tile[32][33];
    const int cb = blockIdx.x * 32, r0 = blockIdx.y * 32;
    const int tx = threadIdx.x, ty = threadIdx.y;
#pragma unroll
    for (int i = ty; i < 32; i += 8)
        tile[i][tx] = in[(size_t)(r0 + i) * C + cb + tx];
    __syncthreads();
#pragma unroll
    for (int i = ty; i < 32; i += 8)
        out[(size_t)(cb + i) * R + r0 + tx] = __float2half_rn(tile[tx][i]);
}

// ---------------------------------------------------------------------------
// Fused transpose of the 3 projection weights [512,512] (z selects tensor)
// ---------------------------------------------------------------------------
__global__ void transpose3_half_kernel(const float* __restrict__ w0,
                                       const float* __restrict__ w1,
                                       const float* __restrict__ w2,
                                       __half* __restrict__ o0,
                                       __half* __restrict__ o1,
                                       __half* __restrict__ o2)
{
    const float* in = (blockIdx.z == 0) ? w0 : (blockIdx.z == 1) ? w1 : w2;
    __half* out = (blockIdx.z == 0) ? o0 : (blockIdx.z == 1) ? o1 : o2;
    __shared__ float tile[32][33];
    const int cb = blockIdx.x * 32, r0 = blockIdx.y * 32;
    const int tx = threadIdx.x, ty = threadIdx.y;
#pragma unroll
    for (int i = ty; i < 32; i += 8)
        tile[i][tx] = in[(size_t)(r0 + i) * 512 + cb + tx];
    __syncthreads();
#pragma unroll
    for (int i = ty; i < 32; i += 8)
        out[(size_t)(cb + i) * 512 + r0 + tx] = __float2half_rn(tile[tx][i]);
}

// ---------------------------------------------------------------------------
// Row softmax (unnormalized) over fp16 scores: E = exp(s - max) fp16,
// invsum = 1/sum(E). One 256-thread block per row of 4096.
// ---------------------------------------------------------------------------
__global__ __launch_bounds__(256) void softmax4096_kernel(
    const __half* __restrict__ S, __half* __restrict__ E,
    float* __restrict__ invsum)
{
    const uint2* row = reinterpret_cast<const uint2*>(S + (size_t)blockIdx.x * 4096);
    const int tid = threadIdx.x;
    __shared__ float red[8];

    float v[4][4];
    float m = -INFINITY;
#pragma unroll
    for (int s = 0; s < 4; s++) {
        uint2 r = row[tid + s * 256];
        float2 lo = __half22float2(*reinterpret_cast<__half2*>(&r.x));
        float2 hi = __half22float2(*reinterpret_cast<__half2*>(&r.y));
        v[s][0] = lo.x; v[s][1] = lo.y; v[s][2] = hi.x; v[s][3] = hi.y;
        m = fmaxf(m, fmaxf(fmaxf(lo.x, lo.y), fmaxf(hi.x, hi.y)));
    }
#pragma unroll
    for (int o = 16; o; o >>= 1) m = fmaxf(m, __shfl_xor_sync(0xffffffffu, m, o));
    if ((tid & 31) == 0) red[tid >> 5] = m;
    __syncthreads();
    float mAll = red[0];
#pragma unroll
    for (int w = 1; w < 8; w++) mAll = fmaxf(mAll, red[w]);
    __syncthreads();

    float sum = 0.f;
#pragma unroll
    for (int s = 0; s < 4; s++) {
#pragma unroll
        for (int c = 0; c < 4; c++) {
            v[s][c] = __expf(v[s][c] - mAll);
            sum += v[s][c];
        }
    }
#pragma unroll
    for (int o = 16; o; o >>= 1) sum += __shfl_xor_sync(0xffffffffu, sum, o);
    if ((tid & 31) == 0) red[tid >> 5] = sum;
    __syncthreads();
    float sAll = 0.f;
#pragma unroll
    for (int w = 0; w < 8; w++) sAll += red[w];
    if (tid == 0) invsum[blockIdx.x] = 1.f / sAll;

    uint2* oe = reinterpret_cast<uint2*>(E + (size_t)blockIdx.x * 4096);
#pragma unroll
    for (int s = 0; s < 4; s++)
        oe[tid + s * 256] =
            make_uint2(pack2h(v[s][0], v[s][1]), pack2h(v[s][2], v[s][3]));
}

// ---------------------------------------------------------------------------
// Launch  (scores GEMM is launch index 5 so ncu -s 5 -c 1 profiles it)
// ---------------------------------------------------------------------------
extern "C" void kernel_launch(void* const* d_in, const int* in_sizes, int n_in,
                              void* d_out, int out_size)
{
    const float* me = (const float*)d_in[0];
    const float* ce = (const float*)d_in[1];
    const float* Wq = (const float*)d_in[2];
    const float* bq = (const float*)d_in[3];
    const float* Wk = (const float*)d_in[4];
    const float* bk = (const float*)d_in[5];
    const float* Wv = (const float*)d_in[6];
    const float* bv = (const float*)d_in[7];
    const float* Wo = (const float*)d_in[8];
    const float* bo = (const float*)d_in[9];
    float* out = (float*)d_out;

    cudaFuncSetAttribute(mm_tc<true,  false, 2>, cudaFuncAttributeMaxDynamicSharedMemorySize, SMEM_SZ);
    cudaFuncSetAttribute(mm_tc<true,  false, 0>, cudaFuncAttributeMaxDynamicSharedMemorySize, SMEM_SZ);
    cudaFuncSetAttribute(mm_tc<false, false, 2>, cudaFuncAttributeMaxDynamicSharedMemorySize, SMEM_SZ);
    cudaFuncSetAttribute(mm_tc<false, true,  2>, cudaFuncAttributeMaxDynamicSharedMemorySize, SMEM_SZ);

    __half *meH, *ceH, *wqt, *wkt, *wvt, *wot, *q, *k, *vt, *s, *e, *x;
    float *v, *invsum;
    cudaGetSymbolAddress((void**)&meH, g_me);
    cudaGetSymbolAddress((void**)&ceH, g_ce);
    cudaGetSymbolAddress((void**)&wqt, g_wqt);
    cudaGetSymbolAddress((void**)&wkt, g_wkt);
    cudaGetSymbolAddress((void**)&wvt, g_wvt);
    cudaGetSymbolAddress((void**)&wot, g_wot);
    cudaGetSymbolAddress((void**)&q, g_q);
    cudaGetSymbolAddress((void**)&k, g_k);
    cudaGetSymbolAddress((void**)&v, g_v);
    cudaGetSymbolAddress((void**)&vt, g_vt);
    cudaGetSymbolAddress((void**)&s, g_s);
    cudaGetSymbolAddress((void**)&e, g_e);
    cudaGetSymbolAddress((void**)&invsum, g_invsum);
    cudaGetSymbolAddress((void**)&x, g_x);

    const int MQ = 16384, Cn = 4096, Ad = 512, Dd = 512, Pd = 512;
    const float scale = 0.044194173824159216f;  // 1/sqrt(512)
    dim3 tb(32, 8);

    // 0-2: converts + fused weight transposes
    convert_half_kernel<<<(MQ * Dd / 4 + 255) / 256, 256>>>(me, meH, MQ * Dd / 4);
    convert_half_kernel<<<(Cn * Dd / 4 + 255) / 256, 256>>>(ce, ceH, Cn * Dd / 4);
    transpose3_half_kernel<<<dim3(16, 16, 3), tb>>>(Wq, Wk, Wv, wqt, wkt, wvt);
    // 3: q = ME @ Wq + bq -> fp16
    mm_tc<true, false, 2><<<dim3(Ad / BN, MQ / BM), 256, SMEM_SZ>>>(
        meH, wqt, bq, nullptr, 1.f, nullptr, q, MQ, Ad, Dd);
    // 4: k = CE @ Wk + bk -> fp16
    mm_tc<true, false, 2><<<dim3(Ad / BN, Cn / BM), 256, SMEM_SZ>>>(
        ceH, wkt, bk, nullptr, 1.f, nullptr, k, Cn, Ad, Dd);
    // 5: s = scale * q @ k^T -> fp16   (ncu profiles this one)
    mm_tc<false, false, 2><<<dim3(Cn / BN, MQ / BM), 256, SMEM_SZ>>>(
        q, k, nullptr, nullptr, scale, nullptr, s, MQ, Cn, Ad);
    // 6: v = CE @ Wv + bv -> fp32
    mm_tc<true, false, 0><<<dim3(Ad / BN, Cn / BM), 256, SMEM_SZ>>>(
        ceH, wvt, bv, nullptr, 1.f, v, nullptr, Cn, Ad, Dd);
    // 7: vt = v^T -> fp16
    transpose_half_kernel<<<dim3(Ad / 32, Cn / 32), tb>>>(v, vt, Cn, Ad);
    // 8: e = exp(s - max), invsum
    softmax4096_kernel<<<MQ, 256>>>(s, e, invsum);
    // 9: x = (e @ vt^T) * invsum -> fp16
    mm_tc<false, true, 2><<<dim3(Ad / BN, MQ / BM), 256, SMEM_SZ>>>(
        e, vt, nullptr, invsum, 1.f, nullptr, x, MQ, Ad, Cn);
    // 10: Wo^T -> fp16
    transpose_half_kernel<<<dim3(16, 16), tb>>>(Wo, wot, Ad, Pd);
    // 11: out = x @ Wo + bo -> fp32
    mm_tc<true, false, 0><<<dim3(Pd / BN, MQ / BM), 256, SMEM_SZ>>>(
        x, wot, bo, nullptr, 1.f, out, nullptr, MQ, Pd, Ad);
}

// round 8
// speedup vs baseline: 6.4144x; 1.1248x over previous
#include <cuda_runtime.h>
#include <cuda_fp16.h>
#include <math.h>
#include <stdint.h>

// B=16, T=1024 (MQ=16384), D=512, C=4096, DC=512, A=512, P=512
//
// All GEMMs single-pass fp16 mma.sync (fp32 accum). Softmax emits
// unnormalized exp fp16 + inv_sum; PV epilogue normalizes. Scores stored fp16.
// BK=64 / 3-stage pipeline: half the barrier count of the BK=32 version.

#define DINL __device__ __forceinline__

// ---------------------------------------------------------------------------
// Scratch
// ---------------------------------------------------------------------------
__device__ __align__(256) __half g_me[16384 * 512];
__device__ __align__(256) __half g_ce[4096 * 512];
__device__ __align__(256) __half g_wqt[512 * 512];
__device__ __align__(256) __half g_wkt[512 * 512];
__device__ __align__(256) __half g_wvt[512 * 512];
__device__ __align__(256) __half g_wot[512 * 512];
__device__ __align__(256) __half g_q[16384 * 512];
__device__ __align__(256) __half g_k[4096 * 512];
__device__ __align__(256) float  g_v[4096 * 512];
__device__ __align__(256) __half g_vt[512 * 4096];
__device__ __align__(256) __half g_s[(size_t)16384 * 4096];
__device__ __align__(256) __half g_e[(size_t)16384 * 4096];
__device__ __align__(256) float  g_invsum[16384];
__device__ __align__(256) __half g_x[16384 * 512];

// ---------------------------------------------------------------------------
// Helpers
// ---------------------------------------------------------------------------
DINL uint32_t smem_u32(const void* p) {
    uint32_t a;
    asm("{ .reg .u64 t; cvta.to.shared.u64 t, %1; cvt.u32.u64 %0, t; }"
        : "=r"(a) : "l"(p));
    return a;
}
DINL void cp16(uint32_t dst, const void* src) {
    asm volatile("cp.async.cg.shared.global [%0], [%1], 16;"
                 :: "r"(dst), "l"(src) : "memory");
}
DINL void cp_commit() { asm volatile("cp.async.commit_group;" ::: "memory"); }
template <int N> DINL void cp_wait() {
    asm volatile("cp.async.wait_group %0;" :: "n"(N) : "memory");
}
DINL void ldsm4(uint32_t* r, uint32_t addr) {
    asm volatile("ldmatrix.sync.aligned.m8n8.x4.shared.b16 {%0,%1,%2,%3}, [%4];"
                 : "=r"(r[0]), "=r"(r[1]), "=r"(r[2]), "=r"(r[3]) : "r"(addr));
}
DINL void mma16816(float* c, const uint32_t* a, uint32_t b0, uint32_t b1) {
    asm volatile(
        "mma.sync.aligned.m16n8k16.row.col.f32.f16.f16.f32 "
        "{%0,%1,%2,%3}, {%4,%5,%6,%7}, {%8,%9}, {%0,%1,%2,%3};"
        : "+f"(c[0]), "+f"(c[1]), "+f"(c[2]), "+f"(c[3])
        : "r"(a[0]), "r"(a[1]), "r"(a[2]), "r"(a[3]), "r"(b0), "r"(b1));
}
DINL uint32_t pack2h(float y0, float y1) {
    __half2 h = __floats2half2_rn(y0, y1);
    return *reinterpret_cast<uint32_t*>(&h);
}

// ---------------------------------------------------------------------------
// fp16 GEMM via mma.sync + ldmatrix: C[M,N] = alpha*(A@B^T)(*rowscale)(+bias)
//   A: [M,K] K-major fp16, B: [N,K] K-major fp16.
//   BM=BN=128, BK=64, 3-stage cp.async, 256 threads, warp grid 4x2,
//   warp tile 32x64. Smem rows 144B (36 banks): 8-row LDSM phases hit
//   distinct bank quads (4r mod 32) -> conflict-free.
//   OUT_MODE: 0 = fp32, 2 = fp16
// ---------------------------------------------------------------------------
constexpr int BM = 128, BN = 128, BK = 64, STAGES = 3;
constexpr int ROWB = 144;
constexpr int STAGE_B = 128 * ROWB;            // 18432 B
constexpr int SMEM_SZ = 2 * STAGES * STAGE_B;  // 110592 B

template <bool HAS_BIAS, bool HAS_RS, int OUT_MODE>
__global__ __launch_bounds__(256, 2) void mm_tc(
    const __half* __restrict__ A, const __half* __restrict__ B,
    const float* __restrict__ bias, const float* __restrict__ rowscale,
    float alpha, float* __restrict__ outF, __half* __restrict__ outH,
    int M, int N, int K)
{
    extern __shared__ char smem[];
    const uint32_t sb = smem_u32(smem);
    const int t = threadIdx.x, wid = t >> 5, lane = t & 31;
    const int wm = wid & 3, wn = wid >> 2;
    const int g = lane >> 2, tq = lane & 3;
    const uint32_t lrow = lane & 15;
    const uint32_t lcol = (lane >> 4) * 16;
    const int rowBase = blockIdx.y * BM, colBase = blockIdx.x * BN;
    const int KT = K / BK;

    float acc[2][8][4];
#pragma unroll
    for (int i = 0; i < 2; i++)
#pragma unroll
        for (int j = 0; j < 8; j++)
#pragma unroll
            for (int c = 0; c < 4; c++) acc[i][j][c] = 0.f;

    auto load_chunk = [&](int kt) {
        const int stage = kt % STAGES;
        const size_t kOff = (size_t)kt * BK;
        const uint32_t aBase = sb + stage * STAGE_B;
        const uint32_t bBase = sb + (STAGES + stage) * STAGE_B;
#pragma unroll
        for (int i = 0; i < 4; i++) {
            const int chunk = t + i * 256;     // 0..1023
            const int row = chunk >> 3;        // 0..127
            const int c16 = chunk & 7;         // 16B columns (8 per row)
            const uint32_t soff = row * ROWB + c16 * 16;
            cp16(aBase + soff, A + (size_t)(rowBase + row) * K + kOff + c16 * 8);
            cp16(bBase + soff, B + (size_t)(colBase + row) * K + kOff + c16 * 8);
        }
        cp_commit();
    };

    for (int i = 0; i < STAGES - 1; i++) load_chunk(i);

    for (int kt = 0; kt < KT; kt++) {
        cp_wait<STAGES - 2>();
        __syncthreads();
        if (kt + STAGES - 1 < KT) load_chunk(kt + STAGES - 1);
        else cp_commit();  // keep group accounting uniform

        const int stage = kt % STAGES;
        const uint32_t aS = sb + stage * STAGE_B;
        const uint32_t bS = sb + (STAGES + stage) * STAGE_B;

#pragma unroll
        for (int kk = 0; kk < BK; kk += 16) {
            uint32_t a[2][4];
            ldsm4(a[0], aS + (wm * 32 + 0  + lrow) * ROWB + kk * 2 + lcol);
            ldsm4(a[1], aS + (wm * 32 + 16 + lrow) * ROWB + kk * 2 + lcol);
#pragma unroll
            for (int j2 = 0; j2 < 4; j2++) {
                uint32_t b[4];
                ldsm4(b, bS + (wn * 64 + j2 * 16 + lrow) * ROWB + kk * 2 + lcol);
                mma16816(acc[0][2 * j2 + 0], a[0], b[0], b[2]);
                mma16816(acc[1][2 * j2 + 0], a[1], b[0], b[2]);
                mma16816(acc[0][2 * j2 + 1], a[0], b[1], b[3]);
                mma16816(acc[1][2 * j2 + 1], a[1], b[1], b[3]);
            }
        }
        __syncthreads();
    }

    // --- epilogue ---
#pragma unroll
    for (int i = 0; i < 2; i++) {
        const int r0 = rowBase + wm * 32 + i * 16 + g;
        float rsA = 1.f, rsB = 1.f;
        if (HAS_RS) { rsA = __ldg(rowscale + r0); rsB = __ldg(rowscale + r0 + 8); }
#pragma unroll
        for (int j = 0; j < 8; j++) {
            const int col = colBase + wn * 64 + j * 8 + 2 * tq;
            float y0 = acc[i][j][0] * alpha, y1 = acc[i][j][1] * alpha;
            float y2 = acc[i][j][2] * alpha, y3 = acc[i][j][3] * alpha;
            if (HAS_RS) { y0 *= rsA; y1 *= rsA; y2 *= rsB; y3 *= rsB; }
            if (HAS_BIAS) {
                const float b0 = __ldg(bias + col), b1 = __ldg(bias + col + 1);
                y0 += b0; y1 += b1; y2 += b0; y3 += b1;
            }
            if (OUT_MODE == 2) {
                *reinterpret_cast<uint32_t*>(outH + (size_t)r0 * N + col) =
                    pack2h(y0, y1);
                *reinterpret_cast<uint32_t*>(outH + (size_t)(r0 + 8) * N + col) =
                    pack2h(y2, y3);
            } else {
                *reinterpret_cast<float2*>(outF + (size_t)r0 * N + col) =
                    make_float2(y0, y1);
                *reinterpret_cast<float2*>(outF + (size_t)(r0 + 8) * N + col) =
                    make_float2(y2, y3);
            }
        }
    }
}

// ---------------------------------------------------------------------------
// fp32 -> fp16 elementwise
// ---------------------------------------------------------------------------
__global__ void convert_half_kernel(const float* __restrict__ in,
                                    __half* __restrict__ o, int n4)
{
    int i = blockIdx.x * blockDim.x + threadIdx.x;
    if (i >= n4) return;
    float4 v = reinterpret_cast<const float4*>(in)[i];
    reinterpret_cast<uint2*>(o)[i] =
        make_uint2(pack2h(v.x, v.y), pack2h(v.z, v.w));
}

// ---------------------------------------------------------------------------
// fp32 [R,C] -> transposed fp16 [C,R]
// ---------------------------------------------------------------------------
__global__ void transpose_half_kernel(const float* __restrict__ in,
                                      __half* __restrict__ out, int R, int C)
{
    __shared__ float tile[32][33];
    const int cb = blockIdx.x * 32, r0 = blockIdx.y * 32;
    const int tx = threadIdx.x, ty = threadIdx.y;
#pragma unroll
    for (int i = ty; i < 32; i += 8)
        tile[i][tx] = in[(size_t)(r0 + i) * C + cb + tx];
    __syncthreads();
#pragma unroll
    for (int i = ty; i < 32; i += 8)
        out[(size_t)(cb + i) * R + r0 + tx] = __float2half_rn(tile[tx][i]);
}

// ---------------------------------------------------------------------------
// Fused transpose of the 3 projection weights [512,512] (z selects tensor)
// ---------------------------------------------------------------------------
__global__ void transpose3_half_kernel(const float* __restrict__ w0,
                                       const float* __restrict__ w1,
                                       const float* __restrict__ w2,
                                       __half* __restrict__ o0,
                                       __half* __restrict__ o1,
                                       __half* __restrict__ o2)
{
    const float* in = (blockIdx.z == 0) ? w0 : (blockIdx.z == 1) ? w1 : w2;
    __half* out = (blockIdx.z == 0) ? o0 : (blockIdx.z == 1) ? o1 : o2;
    __shared__ float tile[32][33];
    const int cb = blockIdx.x * 32, r0 = blockIdx.y * 32;
    const int tx = threadIdx.x, ty = threadIdx.y;
#pragma unroll
    for (int i = ty; i < 32; i += 8)
        tile[i][tx] = in[(size_t)(r0 + i) * 512 + cb + tx];
    __syncthreads();
#pragma unroll
    for (int i = ty; i < 32; i += 8)
        out[(size_t)(cb + i) * 512 + r0 + tx] = __float2half_rn(tile[tx][i]);
}

// ---------------------------------------------------------------------------
// Row softmax (unnormalized) over fp16 scores: E = exp(s - max) fp16,
// invsum = 1/sum(E). One 256-thread block per row of 4096.
// ---------------------------------------------------------------------------
__global__ __launch_bounds__(256) void softmax4096_kernel(
    const __half* __restrict__ S, __half* __restrict__ E,
    float* __restrict__ invsum)
{
    const uint2* row = reinterpret_cast<const uint2*>(S + (size_t)blockIdx.x * 4096);
    const int tid = threadIdx.x;
    __shared__ float red[8];

    float v[4][4];
    float m = -INFINITY;
#pragma unroll
    for (int s = 0; s < 4; s++) {
        uint2 r = row[tid + s * 256];
        float2 lo = __half22float2(*reinterpret_cast<__half2*>(&r.x));
        float2 hi = __half22float2(*reinterpret_cast<__half2*>(&r.y));
        v[s][0] = lo.x; v[s][1] = lo.y; v[s][2] = hi.x; v[s][3] = hi.y;
        m = fmaxf(m, fmaxf(fmaxf(lo.x, lo.y), fmaxf(hi.x, hi.y)));
    }
#pragma unroll
    for (int o = 16; o; o >>= 1) m = fmaxf(m, __shfl_xor_sync(0xffffffffu, m, o));
    if ((tid & 31) == 0) red[tid >> 5] = m;
    __syncthreads();
    float mAll = red[0];
#pragma unroll
    for (int w = 1; w < 8; w++) mAll = fmaxf(mAll, red[w]);
    __syncthreads();

    float sum = 0.f;
#pragma unroll
    for (int s = 0; s < 4; s++) {
#pragma unroll
        for (int c = 0; c < 4; c++) {
            v[s][c] = __expf(v[s][c] - mAll);
            sum += v[s][c];
        }
    }
#pragma unroll
    for (int o = 16; o; o >>= 1) sum += __shfl_xor_sync(0xffffffffu, sum, o);
    if ((tid & 31) == 0) red[tid >> 5] = sum;
    __syncthreads();
    float sAll = 0.f;
#pragma unroll
    for (int w = 0; w < 8; w++) sAll += red[w];
    if (tid == 0) invsum[blockIdx.x] = 1.f / sAll;

    uint2* oe = reinterpret_cast<uint2*>(E + (size_t)blockIdx.x * 4096);
#pragma unroll
    for (int s = 0; s < 4; s++)
        oe[tid + s * 256] =
            make_uint2(pack2h(v[s][0], v[s][1]), pack2h(v[s][2], v[s][3]));
}

// ---------------------------------------------------------------------------
// Launch  (scores GEMM is launch index 5 so ncu -s 5 -c 1 profiles it)
// ---------------------------------------------------------------------------
extern "C" void kernel_launch(void* const* d_in, const int* in_sizes, int n_in,
                              void* d_out, int out_size)
{
    const float* me = (const float*)d_in[0];
    const float* ce = (const float*)d_in[1];
    const float* Wq = (const float*)d_in[2];
    const float* bq = (const float*)d_in[3];
    const float* Wk = (const float*)d_in[4];
    const float* bk = (const float*)d_in[5];
    const float* Wv = (const float*)d_in[6];
    const float* bv = (const float*)d_in[7];
    const float* Wo = (const float*)d_in[8];
    const float* bo = (const float*)d_in[9];
    float* out = (float*)d_out;

    cudaFuncSetAttribute(mm_tc<true,  false, 2>, cudaFuncAttributeMaxDynamicSharedMemorySize, SMEM_SZ);
    cudaFuncSetAttribute(mm_tc<true,  false, 0>, cudaFuncAttributeMaxDynamicSharedMemorySize, SMEM_SZ);
    cudaFuncSetAttribute(mm_tc<false, false, 2>, cudaFuncAttributeMaxDynamicSharedMemorySize, SMEM_SZ);
    cudaFuncSetAttribute(mm_tc<false, true,  2>, cudaFuncAttributeMaxDynamicSharedMemorySize, SMEM_SZ);

    __half *meH, *ceH, *wqt, *wkt, *wvt, *wot, *q, *k, *vt, *s, *e, *x;
    float *v, *invsum;
    cudaGetSymbolAddress((void**)&meH, g_me);
    cudaGetSymbolAddress((void**)&ceH, g_ce);
    cudaGetSymbolAddress((void**)&wqt, g_wqt);
    cudaGetSymbolAddress((void**)&wkt, g_wkt);
    cudaGetSymbolAddress((void**)&wvt, g_wvt);
    cudaGetSymbolAddress((void**)&wot, g_wot);
    cudaGetSymbolAddress((void**)&q, g_q);
    cudaGetSymbolAddress((void**)&k, g_k);
    cudaGetSymbolAddress((void**)&v, g_v);
    cudaGetSymbolAddress((void**)&vt, g_vt);
    cudaGetSymbolAddress((void**)&s, g_s);
    cudaGetSymbolAddress((void**)&e, g_e);
    cudaGetSymbolAddress((void**)&invsum, g_invsum);
    cudaGetSymbolAddress((void**)&x, g_x);

    const int MQ = 16384, Cn = 4096, Ad = 512, Dd = 512, Pd = 512;
    const float scale = 0.044194173824159216f;  // 1/sqrt(512)
    dim3 tb(32, 8);

    // 0-2: converts + fused weight transposes
    convert_half_kernel<<<(MQ * Dd / 4 + 255) / 256, 256>>>(me, meH, MQ * Dd / 4);
    convert_half_kernel<<<(Cn * Dd / 4 + 255) / 256, 256>>>(ce, ceH, Cn * Dd / 4);
    transpose3_half_kernel<<<dim3(16, 16, 3), tb>>>(Wq, Wk, Wv, wqt, wkt, wvt);
    // 3: q = ME @ Wq + bq -> fp16
    mm_tc<true, false, 2><<<dim3(Ad / BN, MQ / BM), 256, SMEM_SZ>>>(
        meH, wqt, bq, nullptr, 1.f, nullptr, q, MQ, Ad, Dd);
    // 4: k = CE @ Wk + bk -> fp16
    mm_tc<true, false, 2><<<dim3(Ad / BN, Cn / BM), 256, SMEM_SZ>>>(
        ceH, wkt, bk, nullptr, 1.f, nullptr, k, Cn, Ad, Dd);
    // 5: s = scale * q @ k^T -> fp16   (ncu profiles this one)
    mm_tc<false, false, 2><<<dim3(Cn / BN, MQ / BM), 256, SMEM_SZ>>>(
        q, k, nullptr, nullptr, scale, nullptr, s, MQ, Cn, Ad);
    // 6: v = CE @ Wv + bv -> fp32
    mm_tc<true, false, 0><<<dim3(Ad / BN, Cn / BM), 256, SMEM_SZ>>>(
        ceH, wvt, bv, nullptr, 1.f, v, nullptr, Cn, Ad, Dd);
    // 7: vt = v^T -> fp16
    transpose_half_kernel<<<dim3(Ad / 32, Cn / 32), tb>>>(v, vt, Cn, Ad);
    // 8: e = exp(s - max), invsum
    softmax4096_kernel<<<MQ, 256>>>(s, e, invsum);
    // 9: x = (e @ vt^T) * invsum -> fp16
    mm_tc<false, true, 2><<<dim3(Ad / BN, MQ / BM), 256, SMEM_SZ>>>(
        e, vt, nullptr, invsum, 1.f, nullptr, x, MQ, Ad, Cn);
    // 10: Wo^T -> fp16
    transpose_half_kernel<<<dim3(16, 16), tb>>>(Wo, wot, Ad, Pd);
    // 11: out = x @ Wo + bo -> fp32
    mm_tc<true, false, 0><<<dim3(Pd / BN, MQ / BM), 256, SMEM_SZ>>>(
        x, wot, bo, nullptr, 1.f, out, nullptr, MQ, Pd, Ad);
}